// round 9
// baseline (speedup 1.0000x reference)
#include <cuda_runtime.h>
#include <cuda_fp16.h>
#include <cstdint>

#define NN   100000
#define NNZE 3200000
#define NIDX 50000

static inline int cdiv(int a, int b) { return (a + b - 1) / b; }

// ---------------- scratch (device globals) -----------------------------------
__device__ int    g_count[NN];
__device__ int    g_row_ptr[NN + 1];
__device__ int    g_cursor[NN];
__device__ int    g_mark[NN];
__device__ int    g_csr_col[NNZE];
__device__ float  g_csr_val[NNZE];
// Basis 1 fp32 for GEMM A: [N][384] = [T0 | T1 | T2]
__device__ float  g_A1[(size_t)NN * 384];
// fp16 gather sources
__device__ __half g_xh[(size_t)NN * 128];
__device__ __half g_T1h[(size_t)NN * 128];
__device__ __half g_Zh[(size_t)NN * 128];   // [0:64)=U, [64:128)=V
__device__ __half g_LVh[(size_t)NN * 64];
// H = relu(basis1 @ W1 + b1), fp32 [N][256]
__device__ float  g_H[(size_t)NN * 256];
// P = H @ (W2_0 - W2_2) + b2, fp32 [N][64]; final pass rewrites rows in place
__device__ float  g_P[(size_t)NN * 64];
// Permuted weights
__device__ float  g_W1p[384 * 256];
__device__ float  g_W2cat[256 * 128];
__device__ float  g_W2d[256 * 64];

// ---------------- setup kernels ---------------------------------------------
__global__ void permute_W1(const float* __restrict__ W1) {
    int i = blockIdx.x * blockDim.x + threadIdx.x;
    if (i >= 384 * 256) return;
    int row = i / 256, j = i % 256;
    int k = row / 128, f = row % 128;
    g_W1p[i] = W1[(f * 3 + k) * 256 + j];
}

__global__ void prep_W2(const float* __restrict__ W2) {
    int i = blockIdx.x * blockDim.x + threadIdx.x;
    if (i < 256 * 128) {
        int f = i / 128, j = i % 128;
        int k = (j < 64) ? 1 : 2;
        int jj = (j < 64) ? j : (j - 64);
        g_W2cat[i] = W2[(f * 3 + k) * 64 + jj];
    }
    if (i < 256 * 64) {
        int f = i / 64, j = i % 64;
        g_W2d[i] = W2[(f * 3 + 0) * 64 + j] - W2[(f * 3 + 2) * 64 + j];
    }
}

__global__ void zero_counts() {
    int i = blockIdx.x * blockDim.x + threadIdx.x;
    if (i < NN) { g_count[i] = 0; g_mark[i] = 0; }
}

__global__ void hist_kernel(const int* __restrict__ rows) {
    int i = blockIdx.x * blockDim.x + threadIdx.x;
    if (i < NNZE) atomicAdd(&g_count[rows[i]], 1);
}

__global__ void scan_kernel() {
    __shared__ int warp_sums[32];
    __shared__ int s_carry;
    int tid = threadIdx.x, lane = tid & 31, wid = tid >> 5;
    if (tid == 0) s_carry = 0;
    __syncthreads();
    for (int base = 0; base < NN; base += 1024) {
        int i = base + tid;
        int v = (i < NN) ? g_count[i] : 0;
        int x = v;
        #pragma unroll
        for (int off = 1; off < 32; off <<= 1) {
            int y = __shfl_up_sync(0xffffffffu, x, off);
            if (lane >= off) x += y;
        }
        if (lane == 31) warp_sums[wid] = x;
        __syncthreads();
        if (wid == 0) {
            int w = warp_sums[lane];
            #pragma unroll
            for (int off = 1; off < 32; off <<= 1) {
                int y = __shfl_up_sync(0xffffffffu, w, off);
                if (lane >= off) w += y;
            }
            warp_sums[lane] = w;
        }
        __syncthreads();
        int warp_off = (wid > 0) ? warp_sums[wid - 1] : 0;
        int incl = x + warp_off + s_carry;
        int excl = incl - v;
        if (i < NN) { g_row_ptr[i] = excl; g_cursor[i] = excl; }
        int tile_total = warp_sums[31];
        __syncthreads();
        if (tid == 0) s_carry += tile_total;
        __syncthreads();
    }
    if (threadIdx.x == 0) g_row_ptr[NN] = s_carry;
}

__global__ void scatter_kernel(const int* __restrict__ rows,
                               const int* __restrict__ cols,
                               const float* __restrict__ vals) {
    int i = blockIdx.x * blockDim.x + threadIdx.x;
    if (i >= NNZE) return;
    int r = rows[i];
    int pos = atomicAdd(&g_cursor[r], 1);
    g_csr_col[pos] = cols[i];
    g_csr_val[pos] = vals[i];
}

__global__ void mark_kernel(const int* __restrict__ idx) {
    int i = blockIdx.x * blockDim.x + threadIdx.x;
    if (i < NIDX) g_mark[idx[i]] = 1;
}

// x -> A1[:,0:128] fp32 and g_xh fp16
__global__ void copy_x(const float* __restrict__ x) {
    int i = blockIdx.x * blockDim.x + threadIdx.x;  // NN*32 float4
    if (i >= NN * 32) return;
    int n = i >> 5, f4 = i & 31;
    float4 v = reinterpret_cast<const float4*>(x)[i];
    reinterpret_cast<float4*>(g_A1 + (size_t)n * 384)[f4] = v;
    __half2 h0 = __floats2half2_rn(v.x, v.y);
    __half2 h1 = __floats2half2_rn(v.z, v.w);
    uint2 u;
    u.x = *reinterpret_cast<uint32_t*>(&h0);
    u.y = *reinterpret_cast<uint32_t*>(&h1);
    reinterpret_cast<uint2*>(g_xh + (size_t)n * 128)[f4] = u;
}

// ---------------- fp16-gather SpMM (128-wide), warp per row -------------------
// acc = sum val * srch[col] (4 floats/lane). Optionally:
//   dual: write acc fp32 to dst (stride 384) and fp16 to dsth
//   sub : write (2*acc - sub) fp32 to dst
__device__ __forceinline__ void gather_add_h128(const __half* __restrict__ srch,
                                                int c, float v, int lane, float4& acc) {
    uint2 u = reinterpret_cast<const uint2*>(srch + (size_t)c * 128)[lane];
    __half2 h0 = *reinterpret_cast<__half2*>(&u.x);
    __half2 h1 = *reinterpret_cast<__half2*>(&u.y);
    float2 f0 = __half22float2(h0);
    float2 f1 = __half22float2(h1);
    acc.x += v * f0.x; acc.y += v * f0.y;
    acc.z += v * f1.x; acc.w += v * f1.y;
}

template <bool DUAL, bool SUB>
__global__ void spmm128_kernel(const __half* __restrict__ srch,
                               float* __restrict__ dst,        // fp32, stride 384
                               __half* __restrict__ dsth,      // fp16, stride 128 (DUAL)
                               const float* __restrict__ sub)  // fp32, stride 384 (SUB)
{
    int gw = (blockIdx.x * blockDim.x + threadIdx.x) >> 5;
    if (gw >= NN) return;
    int lane = threadIdx.x & 31;
    int s = g_row_ptr[gw], e = g_row_ptr[gw + 1];

    float4 acc = make_float4(0.f, 0.f, 0.f, 0.f);
    int i = s;
    for (; i + 3 < e; i += 4) {
        int   c0 = g_csr_col[i],   c1 = g_csr_col[i+1];
        int   c2 = g_csr_col[i+2], c3 = g_csr_col[i+3];
        float v0 = g_csr_val[i],   v1 = g_csr_val[i+1];
        float v2 = g_csr_val[i+2], v3 = g_csr_val[i+3];
        gather_add_h128(srch, c0, v0, lane, acc);
        gather_add_h128(srch, c1, v1, lane, acc);
        gather_add_h128(srch, c2, v2, lane, acc);
        gather_add_h128(srch, c3, v3, lane, acc);
    }
    for (; i < e; i++)
        gather_add_h128(srch, g_csr_col[i], g_csr_val[i], lane, acc);

    if (SUB) {
        float4 sv = reinterpret_cast<const float4*>(sub + (size_t)gw * 384)[lane];
        acc.x = 2.f * acc.x - sv.x;
        acc.y = 2.f * acc.y - sv.y;
        acc.z = 2.f * acc.z - sv.z;
        acc.w = 2.f * acc.w - sv.w;
    }
    reinterpret_cast<float4*>(dst + (size_t)gw * 384)[lane] = acc;
    if (DUAL) {
        __half2 h0 = __floats2half2_rn(acc.x, acc.y);
        __half2 h1 = __floats2half2_rn(acc.z, acc.w);
        uint2 u;
        u.x = *reinterpret_cast<uint32_t*>(&h0);
        u.y = *reinterpret_cast<uint32_t*>(&h1);
        reinterpret_cast<uint2*>(dsth + (size_t)gw * 128)[lane] = u;
    }
}

// ---------------- LV = L @ V  (V = Zh cols 64:128), output fp16 64-wide -------
__global__ void spmm_lv_kernel() {
    int gw = (blockIdx.x * blockDim.x + threadIdx.x) >> 5;
    if (gw >= NN) return;
    int lane = threadIdx.x & 31;
    int s = g_row_ptr[gw], e = g_row_ptr[gw + 1];

    float2 acc = make_float2(0.f, 0.f);
    int i = s;
    for (; i + 3 < e; i += 4) {
        #pragma unroll
        for (int q = 0; q < 4; q++) {
            int c = g_csr_col[i + q];
            float v = g_csr_val[i + q];
            __half2 h = reinterpret_cast<const __half2*>(g_Zh + (size_t)c * 128 + 64)[lane];
            float2 f = __half22float2(h);
            acc.x += v * f.x; acc.y += v * f.y;
        }
    }
    for (; i < e; i++) {
        int c = g_csr_col[i];
        float v = g_csr_val[i];
        __half2 h = reinterpret_cast<const __half2*>(g_Zh + (size_t)c * 128 + 64)[lane];
        float2 f = __half22float2(h);
        acc.x += v * f.x; acc.y += v * f.y;
    }
    reinterpret_cast<__half2*>(g_LVh + (size_t)gw * 64)[lane] =
        __floats2half2_rn(acc.x, acc.y);
}

// ---------------- final: for marked rows, P[r] += LU[r] + 2*(L LV)[r] ---------
__global__ void final_rows_kernel() {
    int gw = (blockIdx.x * blockDim.x + threadIdx.x) >> 5;
    if (gw >= NN) return;
    if (g_mark[gw] == 0) return;
    int lane = threadIdx.x & 31;
    int s = g_row_ptr[gw], e = g_row_ptr[gw + 1];

    float2 aU = make_float2(0.f, 0.f);
    float2 aL = make_float2(0.f, 0.f);
    int i = s;
    for (; i + 1 < e; i += 2) {
        #pragma unroll
        for (int q = 0; q < 2; q++) {
            int c = g_csr_col[i + q];
            float v = g_csr_val[i + q];
            __half2 hu = reinterpret_cast<const __half2*>(g_Zh + (size_t)c * 128)[lane];
            __half2 hl = reinterpret_cast<const __half2*>(g_LVh + (size_t)c * 64)[lane];
            float2 fu = __half22float2(hu);
            float2 fl = __half22float2(hl);
            aU.x += v * fu.x; aU.y += v * fu.y;
            aL.x += v * fl.x; aL.y += v * fl.y;
        }
    }
    if (i < e) {
        int c = g_csr_col[i];
        float v = g_csr_val[i];
        __half2 hu = reinterpret_cast<const __half2*>(g_Zh + (size_t)c * 128)[lane];
        __half2 hl = reinterpret_cast<const __half2*>(g_LVh + (size_t)c * 64)[lane];
        float2 fu = __half22float2(hu);
        float2 fl = __half22float2(hl);
        aU.x += v * fu.x; aU.y += v * fu.y;
        aL.x += v * fl.x; aL.y += v * fl.y;
    }

    float2* pr = reinterpret_cast<float2*>(g_P + (size_t)gw * 64) + lane;
    float2 p = *pr;
    p.x += aU.x + 2.f * aL.x;
    p.y += aU.y + 2.f * aL.y;
    *pr = p;
}

__global__ void gather_out_kernel(const int* __restrict__ idx,
                                  float* __restrict__ out) {
    int i = blockIdx.x * blockDim.x + threadIdx.x;  // NIDX*16 float4
    if (i >= NIDX * 16) return;
    int n = i >> 4, f4 = i & 15;
    int r = idx[n];
    reinterpret_cast<float4*>(out + (size_t)n * 64)[f4] =
        reinterpret_cast<const float4*>(g_P + (size_t)r * 64)[f4];
}

// ---------------- tf32 tensor-core GEMM ---------------------------------------
__device__ __forceinline__ float f2tf32(float x) {
    unsigned u;
    asm("cvt.rna.tf32.f32 %0, %1;" : "=r"(u) : "f"(x));
    return __uint_as_float(u);
}

template <int BM, int BN, int BK, int WM, int WN, bool RELU, bool ADD_BIAS, bool HALF_OUT>
__global__ __launch_bounds__((BM / WM) * (BN / WN) * 32)
void gemm_tf32_kernel(const float* __restrict__ A, int lda,
                      const float* __restrict__ B, int ldb,
                      const float* __restrict__ bias,
                      void* __restrict__ Cv, int ldc,
                      int M, int Ktot) {
    constexpr int WARPS_M = BM / WM;
    constexpr int WARPS_N = BN / WN;
    constexpr int THREADS = WARPS_M * WARPS_N * 32;
    constexpr int MT = WM / 16;
    constexpr int NT = WN / 8;
    constexpr int LDA_S = BM + 2;
    constexpr int LDB_S = BN + 8;

    __shared__ float As[BK][LDA_S];
    __shared__ float Bs[BK][LDB_S];

    int tid = threadIdx.x;
    int lane = tid & 31, wid = tid >> 5;
    int wm = (wid / WARPS_N) * WM;
    int wn = (wid % WARPS_N) * WN;
    int m0 = blockIdx.y * BM;
    int n0 = blockIdx.x * BN;

    float acc[MT][NT][4];
    #pragma unroll
    for (int mt = 0; mt < MT; mt++)
        #pragma unroll
        for (int nt = 0; nt < NT; nt++)
            #pragma unroll
            for (int q = 0; q < 4; q++) acc[mt][nt][q] = 0.f;

    constexpr int A_ITER = BM * BK / 4 / THREADS;
    constexpr int B_ITER = BK * BN / 4 / THREADS;

    for (int k0 = 0; k0 < Ktot; k0 += BK) {
        #pragma unroll
        for (int it = 0; it < A_ITER; it++) {
            int f4 = tid + it * THREADS;
            int ar = f4 / (BK / 4);
            int ac = (f4 % (BK / 4)) * 4;
            float4 v = make_float4(0.f, 0.f, 0.f, 0.f);
            int m = m0 + ar;
            if (m < M)
                v = *reinterpret_cast<const float4*>(A + (size_t)m * lda + k0 + ac);
            As[ac + 0][ar] = f2tf32(v.x);
            As[ac + 1][ar] = f2tf32(v.y);
            As[ac + 2][ar] = f2tf32(v.z);
            As[ac + 3][ar] = f2tf32(v.w);
        }
        #pragma unroll
        for (int it = 0; it < B_ITER; it++) {
            int f4 = tid + it * THREADS;
            int br = f4 / (BN / 4);
            int bc = (f4 % (BN / 4)) * 4;
            float4 v = *reinterpret_cast<const float4*>(B + (size_t)(k0 + br) * ldb + n0 + bc);
            Bs[br][bc + 0] = f2tf32(v.x);
            Bs[br][bc + 1] = f2tf32(v.y);
            Bs[br][bc + 2] = f2tf32(v.z);
            Bs[br][bc + 3] = f2tf32(v.w);
        }
        __syncthreads();
        #pragma unroll
        for (int kk = 0; kk < BK; kk += 8) {
            uint32_t af[MT][4], bf[NT][2];
            int kc = kk + (lane & 3);
            #pragma unroll
            for (int mt = 0; mt < MT; mt++) {
                int r = wm + mt * 16 + (lane >> 2);
                af[mt][0] = __float_as_uint(As[kc][r]);
                af[mt][1] = __float_as_uint(As[kc][r + 8]);
                af[mt][2] = __float_as_uint(As[kc + 4][r]);
                af[mt][3] = __float_as_uint(As[kc + 4][r + 8]);
            }
            #pragma unroll
            for (int nt = 0; nt < NT; nt++) {
                int n = wn + nt * 8 + (lane >> 2);
                bf[nt][0] = __float_as_uint(Bs[kc][n]);
                bf[nt][1] = __float_as_uint(Bs[kc + 4][n]);
            }
            #pragma unroll
            for (int mt = 0; mt < MT; mt++)
                #pragma unroll
                for (int nt = 0; nt < NT; nt++)
                    asm volatile(
                        "mma.sync.aligned.m16n8k8.row.col.f32.tf32.tf32.f32 "
                        "{%0,%1,%2,%3}, {%4,%5,%6,%7}, {%8,%9}, {%0,%1,%2,%3};"
                        : "+f"(acc[mt][nt][0]), "+f"(acc[mt][nt][1]),
                          "+f"(acc[mt][nt][2]), "+f"(acc[mt][nt][3])
                        : "r"(af[mt][0]), "r"(af[mt][1]), "r"(af[mt][2]), "r"(af[mt][3]),
                          "r"(bf[nt][0]), "r"(bf[nt][1]));
        }
        __syncthreads();
    }

    #pragma unroll
    for (int mt = 0; mt < MT; mt++) {
        int r0 = m0 + wm + mt * 16 + (lane >> 2);
        #pragma unroll
        for (int nt = 0; nt < NT; nt++) {
            int n = n0 + wn + nt * 8 + (lane & 3) * 2;
            float bx = 0.f, by = 0.f;
            if (ADD_BIAS) { bx = bias[n]; by = bias[n + 1]; }
            float2 o0, o1;
            o0.x = acc[mt][nt][0] + bx; o0.y = acc[mt][nt][1] + by;
            o1.x = acc[mt][nt][2] + bx; o1.y = acc[mt][nt][3] + by;
            if (RELU) {
                o0.x = fmaxf(o0.x, 0.f); o0.y = fmaxf(o0.y, 0.f);
                o1.x = fmaxf(o1.x, 0.f); o1.y = fmaxf(o1.y, 0.f);
            }
            if (HALF_OUT) {
                __half* C = (__half*)Cv;
                if (r0 < M)
                    *reinterpret_cast<__half2*>(C + (size_t)r0 * ldc + n) =
                        __floats2half2_rn(o0.x, o0.y);
                if (r0 + 8 < M)
                    *reinterpret_cast<__half2*>(C + (size_t)(r0 + 8) * ldc + n) =
                        __floats2half2_rn(o1.x, o1.y);
            } else {
                float* C = (float*)Cv;
                if (r0 < M)
                    *reinterpret_cast<float2*>(C + (size_t)r0 * ldc + n) = o0;
                if (r0 + 8 < M)
                    *reinterpret_cast<float2*>(C + (size_t)(r0 + 8) * ldc + n) = o1;
            }
        }
    }
}

// ---------------- launch ------------------------------------------------------
extern "C" void kernel_launch(void* const* d_in, const int* in_sizes, int n_in,
                              void* d_out, int out_size) {
    const float* x    = (const float*)d_in[0];
    const float* vals = (const float*)d_in[1];
    const float* W1   = (const float*)d_in[2];
    const float* b1   = (const float*)d_in[3];
    const float* W2   = (const float*)d_in[4];
    const float* b2   = (const float*)d_in[5];
    const int*   rows = (const int*)d_in[6];
    const int*   cols = (const int*)d_in[7];
    const int*   idx  = (const int*)d_in[8];
    float*       out  = (float*)d_out;

    float *a1, *h, *p, *w1p, *w2cat, *w2d;
    __half *xh, *t1h, *zh;
    cudaGetSymbolAddress((void**)&a1,    g_A1);
    cudaGetSymbolAddress((void**)&h,     g_H);
    cudaGetSymbolAddress((void**)&p,     g_P);
    cudaGetSymbolAddress((void**)&w1p,   g_W1p);
    cudaGetSymbolAddress((void**)&w2cat, g_W2cat);
    cudaGetSymbolAddress((void**)&w2d,   g_W2d);
    cudaGetSymbolAddress((void**)&xh,    g_xh);
    cudaGetSymbolAddress((void**)&t1h,   g_T1h);
    cudaGetSymbolAddress((void**)&zh,    g_Zh);

    // CSR build + weight prep
    permute_W1<<<cdiv(384 * 256, 256), 256>>>(W1);
    prep_W2<<<cdiv(256 * 128, 256), 256>>>(W2);
    zero_counts<<<cdiv(NN, 256), 256>>>();
    hist_kernel<<<cdiv(NNZE, 256), 256>>>(rows);
    scan_kernel<<<1, 1024>>>();
    scatter_kernel<<<cdiv(NNZE, 256), 256>>>(rows, cols, vals);
    mark_kernel<<<cdiv(NIDX, 256), 256>>>(idx);

    // Layer-1 basis (fp16 gathers, fp32 accumulate)
    copy_x<<<cdiv(NN * 32, 256), 256>>>(x);
    int warp_blocks = cdiv(NN * 32, 256);
    // T1 = L x  -> A1[:,128:256] fp32 + T1h fp16
    spmm128_kernel<true, false><<<warp_blocks, 256>>>(xh, a1 + 128, t1h, nullptr);
    // T2 = 2 L T1 - x -> A1[:,256:384] fp32
    spmm128_kernel<false, true><<<warp_blocks, 256>>>(t1h, a1 + 256, nullptr, a1);

    // H = relu(Basis1 @ W1p + b1), fp32 stride 256
    {
        dim3 grid(256 / 128, cdiv(NN, 128));
        gemm_tf32_kernel<128, 128, 32, 32, 64, true, true, false><<<grid, 256>>>(
            a1, 384, w1p, 256, b1, h, 256, NN, 384);
    }
    // Z = H @ [W2_1 | W2_2] -> fp16 [N][128]
    {
        dim3 grid(1, cdiv(NN, 128));
        gemm_tf32_kernel<128, 128, 32, 32, 64, false, false, true><<<grid, 256>>>(
            h, 256, w2cat, 128, nullptr, zh, 128, NN, 256);
    }
    // P = H @ (W2_0 - W2_2) + b2 -> fp32 [N][64]
    {
        dim3 grid(1, cdiv(NN, 128));
        gemm_tf32_kernel<128, 64, 32, 32, 32, false, true, false><<<grid, 256>>>(
            h, 256, w2d, 64, b2, p, 64, NN, 256);
    }

    // LV = L @ V (fp16 out)
    spmm_lv_kernel<<<warp_blocks, 256>>>();
    // marked rows: P[r] += LU[r] + 2*(L LV)[r]
    final_rows_kernel<<<warp_blocks, 256>>>();
    // out[i] = P[idx[i]]
    gather_out_kernel<<<cdiv(NIDX * 16, 256), 256>>>(idx, out);
}

// round 10
// speedup vs baseline: 1.0700x; 1.0700x over previous
#include <cuda_runtime.h>
#include <cuda_fp16.h>
#include <cstdint>

#define NN   100000
#define NNZE 3200000
#define NIDX 50000

static inline int cdiv(int a, int b) { return (a + b - 1) / b; }

// ---------------- scratch (device globals) -----------------------------------
__device__ int    g_count[NN];
__device__ int    g_row_ptr[NN + 1];
__device__ int    g_cursor[NN];
__device__ int    g_mark[NN];
__device__ int2   g_csr[NNZE];              // (col, val bits) packed
// fp16 basis: [N][384] = [x | T1 | T2]
__device__ __half g_Bh[(size_t)NN * 384];
// fp16 hidden: [N][256]
__device__ __half g_Hh[(size_t)NN * 256];
// fp16 Z: [N][128]  ([0:64)=U, [64:128)=V)
__device__ __half g_Zh[(size_t)NN * 128];
__device__ __half g_LVh[(size_t)NN * 64];
// P = H @ (W2_0 - W2_2) + b2, fp32; final pass accumulates in place
__device__ float  g_P[(size_t)NN * 64];
// Permuted weights (fp32; converted to tf32 at GEMM load)
__device__ float  g_W1p[384 * 256];
__device__ float  g_W2cat[256 * 128];
__device__ float  g_W2d[256 * 64];

// ---------------- helpers -----------------------------------------------------
__device__ __forceinline__ float4 h4_to_f4(uint2 u) {
    __half2 h0 = *reinterpret_cast<__half2*>(&u.x);
    __half2 h1 = *reinterpret_cast<__half2*>(&u.y);
    float2 a = __half22float2(h0);
    float2 b = __half22float2(h1);
    return make_float4(a.x, a.y, b.x, b.y);
}
__device__ __forceinline__ uint2 f4_to_h4(float4 v) {
    __half2 h0 = __floats2half2_rn(v.x, v.y);
    __half2 h1 = __floats2half2_rn(v.z, v.w);
    uint2 u;
    u.x = *reinterpret_cast<uint32_t*>(&h0);
    u.y = *reinterpret_cast<uint32_t*>(&h1);
    return u;
}
__device__ __forceinline__ float f2tf32(float x) {
    unsigned u;
    asm("cvt.rna.tf32.f32 %0, %1;" : "=r"(u) : "f"(x));
    return __uint_as_float(u);
}

// ---------------- setup kernels ------------------------------------------------
// zero counts/marks + permute W1 + prep W2 (one kernel, disjoint index ranges)
__global__ void prep_small(const float* __restrict__ W1,
                           const float* __restrict__ W2) {
    int i = blockIdx.x * blockDim.x + threadIdx.x;
    if (i < NN) { g_count[i] = 0; g_mark[i] = 0; }
    if (i < 384 * 256) {
        int row = i / 256, j = i % 256;
        int k = row / 128, f = row % 128;
        g_W1p[i] = W1[(f * 3 + k) * 256 + j];
    }
    if (i < 256 * 128) {
        int f = i / 128, j = i % 128;
        int k = (j < 64) ? 1 : 2;
        int jj = (j < 64) ? j : (j - 64);
        g_W2cat[i] = W2[(f * 3 + k) * 64 + jj];
    }
    if (i < 256 * 64) {
        int f = i / 64, j = i % 64;
        g_W2d[i] = W2[(f * 3 + 0) * 64 + j] - W2[(f * 3 + 2) * 64 + j];
    }
}

__global__ void hist_kernel(const int* __restrict__ rows) {
    int i = blockIdx.x * blockDim.x + threadIdx.x;
    if (i < NNZE) atomicAdd(&g_count[rows[i]], 1);
}

__global__ void scan_kernel() {
    __shared__ int warp_sums[32];
    __shared__ int s_carry;
    int tid = threadIdx.x, lane = tid & 31, wid = tid >> 5;
    if (tid == 0) s_carry = 0;
    __syncthreads();
    for (int base = 0; base < NN; base += 1024) {
        int i = base + tid;
        int v = (i < NN) ? g_count[i] : 0;
        int x = v;
        #pragma unroll
        for (int off = 1; off < 32; off <<= 1) {
            int y = __shfl_up_sync(0xffffffffu, x, off);
            if (lane >= off) x += y;
        }
        if (lane == 31) warp_sums[wid] = x;
        __syncthreads();
        if (wid == 0) {
            int w = warp_sums[lane];
            #pragma unroll
            for (int off = 1; off < 32; off <<= 1) {
                int y = __shfl_up_sync(0xffffffffu, w, off);
                if (lane >= off) w += y;
            }
            warp_sums[lane] = w;
        }
        __syncthreads();
        int warp_off = (wid > 0) ? warp_sums[wid - 1] : 0;
        int incl = x + warp_off + s_carry;
        int excl = incl - v;
        if (i < NN) { g_row_ptr[i] = excl; g_cursor[i] = excl; }
        int tile_total = warp_sums[31];
        __syncthreads();
        if (tid == 0) s_carry += tile_total;
        __syncthreads();
    }
    if (threadIdx.x == 0) g_row_ptr[NN] = s_carry;
}

__global__ void scatter_kernel(const int* __restrict__ rows,
                               const int* __restrict__ cols,
                               const float* __restrict__ vals) {
    int i = blockIdx.x * blockDim.x + threadIdx.x;
    if (i >= NNZE) return;
    int r = rows[i];
    int pos = atomicAdd(&g_cursor[r], 1);
    g_csr[pos] = make_int2(cols[i], __float_as_int(vals[i]));
}

__global__ void mark_kernel(const int* __restrict__ idx) {
    int i = blockIdx.x * blockDim.x + threadIdx.x;
    if (i < NIDX) g_mark[idx[i]] = 1;
}

// x (fp32) -> Bh[:,0:128] fp16
__global__ void copy_xh(const float* __restrict__ x) {
    int i = blockIdx.x * blockDim.x + threadIdx.x;  // NN*32 float4 groups
    if (i >= NN * 32) return;
    int n = i >> 5, f4 = i & 31;
    float4 v = reinterpret_cast<const float4*>(x)[i];
    reinterpret_cast<uint2*>(g_Bh + (size_t)n * 384)[f4] = f4_to_h4(v);
}

// ---------------- SpMM over the fp16 basis buffer ------------------------------
// dst = L @ src (128-wide). SUB: dst = 2*(L@src) - Bh[:,0:128].
template <bool SUB>
__global__ void spmm_bh_kernel(int src_off, int dst_off) {
    int gw = (blockIdx.x * blockDim.x + threadIdx.x) >> 5;
    if (gw >= NN) return;
    int lane = threadIdx.x & 31;
    int s = g_row_ptr[gw], e = g_row_ptr[gw + 1];

    float4 acc = make_float4(0.f, 0.f, 0.f, 0.f);
    int i = s;
    for (; i + 3 < e; i += 4) {
        #pragma unroll
        for (int q = 0; q < 4; q++) {
            int2 ev = g_csr[i + q];
            float v = __int_as_float(ev.y);
            uint2 u = *reinterpret_cast<const uint2*>(
                g_Bh + (size_t)ev.x * 384 + src_off + lane * 4);
            float4 f = h4_to_f4(u);
            acc.x += v * f.x; acc.y += v * f.y;
            acc.z += v * f.z; acc.w += v * f.w;
        }
    }
    for (; i < e; i++) {
        int2 ev = g_csr[i];
        float v = __int_as_float(ev.y);
        uint2 u = *reinterpret_cast<const uint2*>(
            g_Bh + (size_t)ev.x * 384 + src_off + lane * 4);
        float4 f = h4_to_f4(u);
        acc.x += v * f.x; acc.y += v * f.y;
        acc.z += v * f.z; acc.w += v * f.w;
    }

    if (SUB) {
        uint2 su = *reinterpret_cast<const uint2*>(
            g_Bh + (size_t)gw * 384 + lane * 4);
        float4 sv = h4_to_f4(su);
        acc.x = 2.f * acc.x - sv.x;
        acc.y = 2.f * acc.y - sv.y;
        acc.z = 2.f * acc.z - sv.z;
        acc.w = 2.f * acc.w - sv.w;
    }
    *reinterpret_cast<uint2*>(g_Bh + (size_t)gw * 384 + dst_off + lane * 4) =
        f4_to_h4(acc);
}

// ---------------- LV = L @ V  (V = Zh cols 64:128), fp16 64-wide ---------------
__global__ void spmm_lv_kernel() {
    int gw = (blockIdx.x * blockDim.x + threadIdx.x) >> 5;
    if (gw >= NN) return;
    int lane = threadIdx.x & 31;
    int s = g_row_ptr[gw], e = g_row_ptr[gw + 1];

    float2 acc = make_float2(0.f, 0.f);
    int i = s;
    for (; i + 3 < e; i += 4) {
        #pragma unroll
        for (int q = 0; q < 4; q++) {
            int2 ev = g_csr[i + q];
            float v = __int_as_float(ev.y);
            __half2 h = *reinterpret_cast<const __half2*>(
                g_Zh + (size_t)ev.x * 128 + 64 + lane * 2);
            float2 f = __half22float2(h);
            acc.x += v * f.x; acc.y += v * f.y;
        }
    }
    for (; i < e; i++) {
        int2 ev = g_csr[i];
        float v = __int_as_float(ev.y);
        __half2 h = *reinterpret_cast<const __half2*>(
            g_Zh + (size_t)ev.x * 128 + 64 + lane * 2);
        float2 f = __half22float2(h);
        acc.x += v * f.x; acc.y += v * f.y;
    }
    *reinterpret_cast<__half2*>(g_LVh + (size_t)gw * 64 + lane * 2) =
        __floats2half2_rn(acc.x, acc.y);
}

// ---------------- final: for marked rows, P[r] += LU[r] + 2*(L LV)[r] ----------
__global__ void final_rows_kernel() {
    int gw = (blockIdx.x * blockDim.x + threadIdx.x) >> 5;
    if (gw >= NN) return;
    if (g_mark[gw] == 0) return;
    int lane = threadIdx.x & 31;
    int s = g_row_ptr[gw], e = g_row_ptr[gw + 1];

    float2 aU = make_float2(0.f, 0.f);
    float2 aL = make_float2(0.f, 0.f);
    int i = s;
    for (; i + 1 < e; i += 2) {
        #pragma unroll
        for (int q = 0; q < 2; q++) {
            int2 ev = g_csr[i + q];
            float v = __int_as_float(ev.y);
            __half2 hu = *reinterpret_cast<const __half2*>(
                g_Zh + (size_t)ev.x * 128 + lane * 2);
            __half2 hl = *reinterpret_cast<const __half2*>(
                g_LVh + (size_t)ev.x * 64 + lane * 2);
            float2 fu = __half22float2(hu);
            float2 fl = __half22float2(hl);
            aU.x += v * fu.x; aU.y += v * fu.y;
            aL.x += v * fl.x; aL.y += v * fl.y;
        }
    }
    if (i < e) {
        int2 ev = g_csr[i];
        float v = __int_as_float(ev.y);
        __half2 hu = *reinterpret_cast<const __half2*>(
            g_Zh + (size_t)ev.x * 128 + lane * 2);
        __half2 hl = *reinterpret_cast<const __half2*>(
            g_LVh + (size_t)ev.x * 64 + lane * 2);
        float2 fu = __half22float2(hu);
        float2 fl = __half22float2(hl);
        aU.x += v * fu.x; aU.y += v * fu.y;
        aL.x += v * fl.x; aL.y += v * fl.y;
    }

    float2* pr = reinterpret_cast<float2*>(g_P + (size_t)gw * 64) + lane;
    float2 p = *pr;
    p.x += aU.x + 2.f * aL.x;
    p.y += aU.y + 2.f * aL.y;
    *pr = p;
}

__global__ void gather_out_kernel(const int* __restrict__ idx,
                                  float* __restrict__ out) {
    int i = blockIdx.x * blockDim.x + threadIdx.x;  // NIDX*16 float4
    if (i >= NIDX * 16) return;
    int n = i >> 4, f4 = i & 15;
    int r = idx[n];
    reinterpret_cast<float4*>(out + (size_t)n * 64)[f4] =
        reinterpret_cast<const float4*>(g_P + (size_t)r * 64)[f4];
}

// ---------------- tf32 tensor-core GEMM, fp16 A-operand ------------------------
template <int BM, int BN, int BK, int WM, int WN, bool RELU, bool ADD_BIAS, bool HALF_OUT>
__global__ __launch_bounds__((BM / WM) * (BN / WN) * 32)
void gemm_tf32_kernel(const __half* __restrict__ A, int lda,
                      const float* __restrict__ B, int ldb,
                      const float* __restrict__ bias,
                      void* __restrict__ Cv, int ldc,
                      int M, int Ktot) {
    constexpr int WARPS_M = BM / WM;
    constexpr int WARPS_N = BN / WN;
    constexpr int THREADS = WARPS_M * WARPS_N * 32;
    constexpr int MT = WM / 16;
    constexpr int NT = WN / 8;
    constexpr int LDA_S = BM + 2;
    constexpr int LDB_S = BN + 8;

    __shared__ float As[BK][LDA_S];
    __shared__ float Bs[BK][LDB_S];

    int tid = threadIdx.x;
    int lane = tid & 31, wid = tid >> 5;
    int wm = (wid / WARPS_N) * WM;
    int wn = (wid % WARPS_N) * WN;
    int m0 = blockIdx.y * BM;
    int n0 = blockIdx.x * BN;

    float acc[MT][NT][4];
    #pragma unroll
    for (int mt = 0; mt < MT; mt++)
        #pragma unroll
        for (int nt = 0; nt < NT; nt++)
            #pragma unroll
            for (int q = 0; q < 4; q++) acc[mt][nt][q] = 0.f;

    constexpr int A_ITER = BM * BK / 4 / THREADS;
    constexpr int B_ITER = BK * BN / 4 / THREADS;

    for (int k0 = 0; k0 < Ktot; k0 += BK) {
        #pragma unroll
        for (int it = 0; it < A_ITER; it++) {
            int f4 = tid + it * THREADS;
            int ar = f4 / (BK / 4);
            int ac = (f4 % (BK / 4)) * 4;
            float4 v = make_float4(0.f, 0.f, 0.f, 0.f);
            int m = m0 + ar;
            if (m < M) {
                uint2 u = *reinterpret_cast<const uint2*>(A + (size_t)m * lda + k0 + ac);
                v = h4_to_f4(u);   // fp16 -> f32 is exact; value already tf32-representable
            }
            As[ac + 0][ar] = v.x;
            As[ac + 1][ar] = v.y;
            As[ac + 2][ar] = v.z;
            As[ac + 3][ar] = v.w;
        }
        #pragma unroll
        for (int it = 0; it < B_ITER; it++) {
            int f4 = tid + it * THREADS;
            int br = f4 / (BN / 4);
            int bc = (f4 % (BN / 4)) * 4;
            float4 v = *reinterpret_cast<const float4*>(B + (size_t)(k0 + br) * ldb + n0 + bc);
            Bs[br][bc + 0] = f2tf32(v.x);
            Bs[br][bc + 1] = f2tf32(v.y);
            Bs[br][bc + 2] = f2tf32(v.z);
            Bs[br][bc + 3] = f2tf32(v.w);
        }
        __syncthreads();
        #pragma unroll
        for (int kk = 0; kk < BK; kk += 8) {
            uint32_t af[MT][4], bf[NT][2];
            int kc = kk + (lane & 3);
            #pragma unroll
            for (int mt = 0; mt < MT; mt++) {
                int r = wm + mt * 16 + (lane >> 2);
                af[mt][0] = __float_as_uint(As[kc][r]);
                af[mt][1] = __float_as_uint(As[kc][r + 8]);
                af[mt][2] = __float_as_uint(As[kc + 4][r]);
                af[mt][3] = __float_as_uint(As[kc + 4][r + 8]);
            }
            #pragma unroll
            for (int nt = 0; nt < NT; nt++) {
                int n = wn + nt * 8 + (lane >> 2);
                bf[nt][0] = __float_as_uint(Bs[kc][n]);
                bf[nt][1] = __float_as_uint(Bs[kc + 4][n]);
            }
            #pragma unroll
            for (int mt = 0; mt < MT; mt++)
                #pragma unroll
                for (int nt = 0; nt < NT; nt++)
                    asm volatile(
                        "mma.sync.aligned.m16n8k8.row.col.f32.tf32.tf32.f32 "
                        "{%0,%1,%2,%3}, {%4,%5,%6,%7}, {%8,%9}, {%0,%1,%2,%3};"
                        : "+f"(acc[mt][nt][0]), "+f"(acc[mt][nt][1]),
                          "+f"(acc[mt][nt][2]), "+f"(acc[mt][nt][3])
                        : "r"(af[mt][0]), "r"(af[mt][1]), "r"(af[mt][2]), "r"(af[mt][3]),
                          "r"(bf[nt][0]), "r"(bf[nt][1]));
        }
        __syncthreads();
    }

    #pragma unroll
    for (int mt = 0; mt < MT; mt++) {
        int r0 = m0 + wm + mt * 16 + (lane >> 2);
        #pragma unroll
        for (int nt = 0; nt < NT; nt++) {
            int n = n0 + wn + nt * 8 + (lane & 3) * 2;
            float bx = 0.f, by = 0.f;
            if (ADD_BIAS) { bx = bias[n]; by = bias[n + 1]; }
            float2 o0, o1;
            o0.x = acc[mt][nt][0] + bx; o0.y = acc[mt][nt][1] + by;
            o1.x = acc[mt][nt][2] + bx; o1.y = acc[mt][nt][3] + by;
            if (RELU) {
                o0.x = fmaxf(o0.x, 0.f); o0.y = fmaxf(o0.y, 0.f);
                o1.x = fmaxf(o1.x, 0.f); o1.y = fmaxf(o1.y, 0.f);
            }
            if (HALF_OUT) {
                __half* C = (__half*)Cv;
                if (r0 < M)
                    *reinterpret_cast<__half2*>(C + (size_t)r0 * ldc + n) =
                        __floats2half2_rn(o0.x, o0.y);
                if (r0 + 8 < M)
                    *reinterpret_cast<__half2*>(C + (size_t)(r0 + 8) * ldc + n) =
                        __floats2half2_rn(o1.x, o1.y);
            } else {
                float* C = (float*)Cv;
                if (r0 < M)
                    *reinterpret_cast<float2*>(C + (size_t)r0 * ldc + n) = o0;
                if (r0 + 8 < M)
                    *reinterpret_cast<float2*>(C + (size_t)(r0 + 8) * ldc + n) = o1;
            }
        }
    }
}

// ---------------- launch --------------------------------------------------------
extern "C" void kernel_launch(void* const* d_in, const int* in_sizes, int n_in,
                              void* d_out, int out_size) {
    const float* x    = (const float*)d_in[0];
    const float* vals = (const float*)d_in[1];
    const float* W1   = (const float*)d_in[2];
    const float* b1   = (const float*)d_in[3];
    const float* W2   = (const float*)d_in[4];
    const float* b2   = (const float*)d_in[5];
    const int*   rows = (const int*)d_in[6];
    const int*   cols = (const int*)d_in[7];
    const int*   idx  = (const int*)d_in[8];
    float*       out  = (float*)d_out;

    float  *p, *w1p, *w2cat, *w2d;
    __half *bh, *hh, *zh;
    cudaGetSymbolAddress((void**)&p,     g_P);
    cudaGetSymbolAddress((void**)&w1p,   g_W1p);
    cudaGetSymbolAddress((void**)&w2cat, g_W2cat);
    cudaGetSymbolAddress((void**)&w2d,   g_W2d);
    cudaGetSymbolAddress((void**)&bh,    g_Bh);
    cudaGetSymbolAddress((void**)&hh,    g_Hh);
    cudaGetSymbolAddress((void**)&zh,    g_Zh);

    int warp_blocks = cdiv(NN * 32, 256);

    // 0: zero counts/marks + weight permutes
    prep_small<<<cdiv(NN, 256), 256>>>(W1, W2);
    // 1-3: CSR build (scatter placed at code index 3 for ncu visibility)
    hist_kernel<<<cdiv(NNZE, 256), 256>>>(rows);
    scan_kernel<<<1, 1024>>>();
    scatter_kernel<<<cdiv(NNZE, 256), 256>>>(rows, cols, vals);
    // 4: x -> fp16 basis slot 0
    copy_xh<<<cdiv(NN * 32, 256), 256>>>(x);
    // 5: T1 = L x       (fp16 in, fp16 out)
    spmm_bh_kernel<false><<<warp_blocks, 256>>>(0, 128);
    // 6: T2 = 2 L T1 - x
    spmm_bh_kernel<true><<<warp_blocks, 256>>>(128, 256);

    // 7: H = relu(Basis @ W1p + b1) -> fp16
    {
        dim3 grid(256 / 128, cdiv(NN, 128));
        gemm_tf32_kernel<128, 128, 32, 32, 64, true, true, true><<<grid, 256>>>(
            bh, 384, w1p, 256, b1, hh, 256, NN, 384);
    }
    // 8: Z = H @ [W2_1 | W2_2] -> fp16
    {
        dim3 grid(1, cdiv(NN, 128));
        gemm_tf32_kernel<128, 128, 32, 32, 64, false, false, true><<<grid, 256>>>(
            hh, 256, w2cat, 128, nullptr, zh, 128, NN, 256);
    }
    // 9: P = H @ (W2_0 - W2_2) + b2 -> fp32
    {
        dim3 grid(1, cdiv(NN, 128));
        gemm_tf32_kernel<128, 64, 32, 32, 32, false, true, false><<<grid, 256>>>(
            hh, 256, w2d, 64, b2, p, 64, NN, 256);
    }

    // 10: mark rows needed by the output
    mark_kernel<<<cdiv(NIDX, 256), 256>>>(idx);
    // 11: LV = L @ V
    spmm_lv_kernel<<<warp_blocks, 256>>>();
    // 12: marked rows: P[r] += LU[r] + 2*(L LV)[r]
    final_rows_kernel<<<warp_blocks, 256>>>();
    // 13: out[i] = P[idx[i]]
    gather_out_kernel<<<cdiv(NIDX * 16, 256), 256>>>(idx, out);
}

// round 11
// speedup vs baseline: 1.3487x; 1.2605x over previous
#include <cuda_runtime.h>
#include <cuda_fp16.h>
#include <cstdint>

#define NN   100000
#define NNZE 3200000
#define NIDX 50000

static inline int cdiv(int a, int b) { return (a + b - 1) / b; }

// ---------------- scratch (device globals; zero-initialized at module load) ----
__device__ int    g_count[NN];      // re-zeroed by scan_kernel every call
__device__ int    g_row_ptr[NN + 1];
__device__ int    g_cursor[NN];
__device__ int    g_mark[NN];       // set by prep_w, cleared by final_rows
__device__ int2   g_csr[NNZE];      // (col, val bits)
// fp16 basis: [N][384] = [x | T1 | T2]
__device__ __half g_Bh[(size_t)NN * 384];
// fp16 hidden: [N][256]
__device__ __half g_Hh[(size_t)NN * 256];
// fp16 Z: [N][128]  ([0:64)=U, [64:128)=V)
__device__ __half g_Zh[(size_t)NN * 128];
__device__ __half g_LVh[(size_t)NN * 64];
// P = H @ (W2_0 - W2_2) + b2, fp32; final pass accumulates in place
__device__ float  g_P[(size_t)NN * 64];
// fp16 transposed weights (n-major, K contiguous)
__device__ __half g_W1t[256 * 384];    // [j][k*128+f]
__device__ __half g_W2catT[128 * 256]; // [j][f]
__device__ __half g_W2dT[64 * 256];    // [j][f]

// ---------------- helpers -------------------------------------------------------
__device__ __forceinline__ float4 h4_to_f4(uint2 u) {
    __half2 h0 = *reinterpret_cast<__half2*>(&u.x);
    __half2 h1 = *reinterpret_cast<__half2*>(&u.y);
    float2 a = __half22float2(h0);
    float2 b = __half22float2(h1);
    return make_float4(a.x, a.y, b.x, b.y);
}
__device__ __forceinline__ uint2 f4_to_h4(float4 v) {
    __half2 h0 = __floats2half2_rn(v.x, v.y);
    __half2 h1 = __floats2half2_rn(v.z, v.w);
    uint2 u;
    u.x = *reinterpret_cast<uint32_t*>(&h0);
    u.y = *reinterpret_cast<uint32_t*>(&h1);
    return u;
}

// ---------------- CSR build ------------------------------------------------------
__global__ void hist_kernel(const int* __restrict__ rows) {
    int i = blockIdx.x * blockDim.x + threadIdx.x;
    if (i < NNZE) atomicAdd(&g_count[rows[i]], 1);
}

// scan + re-zero counts (self-cleaning for the next call)
__global__ void scan_kernel() {
    __shared__ int warp_sums[32];
    __shared__ int s_carry;
    int tid = threadIdx.x, lane = tid & 31, wid = tid >> 5;
    if (tid == 0) s_carry = 0;
    __syncthreads();
    for (int base = 0; base < NN; base += 1024) {
        int i = base + tid;
        int v = (i < NN) ? g_count[i] : 0;
        if (i < NN) g_count[i] = 0;
        int x = v;
        #pragma unroll
        for (int off = 1; off < 32; off <<= 1) {
            int y = __shfl_up_sync(0xffffffffu, x, off);
            if (lane >= off) x += y;
        }
        if (lane == 31) warp_sums[wid] = x;
        __syncthreads();
        if (wid == 0) {
            int w = warp_sums[lane];
            #pragma unroll
            for (int off = 1; off < 32; off <<= 1) {
                int y = __shfl_up_sync(0xffffffffu, w, off);
                if (lane >= off) w += y;
            }
            warp_sums[lane] = w;
        }
        __syncthreads();
        int warp_off = (wid > 0) ? warp_sums[wid - 1] : 0;
        int incl = x + warp_off + s_carry;
        int excl = incl - v;
        if (i < NN) { g_row_ptr[i] = excl; g_cursor[i] = excl; }
        int tile_total = warp_sums[31];
        __syncthreads();
        if (tid == 0) s_carry += tile_total;
        __syncthreads();
    }
    if (threadIdx.x == 0) g_row_ptr[NN] = s_carry;
}

// scatter CSR entries AND copy x -> fp16 basis slot 0 (same 3.2M-thread grid)
__global__ void scatter_copyx_kernel(const int* __restrict__ rows,
                                     const int* __restrict__ cols,
                                     const float* __restrict__ vals,
                                     const float* __restrict__ x) {
    int i = blockIdx.x * blockDim.x + threadIdx.x;
    if (i < NNZE) {
        int r = rows[i];
        int pos = atomicAdd(&g_cursor[r], 1);
        g_csr[pos] = make_int2(cols[i], __float_as_int(vals[i]));
    }
    if (i < NN * 32) {
        int n = i >> 5, f4 = i & 31;
        float4 v = reinterpret_cast<const float4*>(x)[i];
        reinterpret_cast<uint2*>(g_Bh + (size_t)n * 384)[f4] = f4_to_h4(v);
    }
}

// weight prep (fp16, transposed to n-major) + output-row marking
__global__ void prep_w_kernel(const float* __restrict__ W1,
                              const float* __restrict__ W2,
                              const int* __restrict__ idx) {
    int i = blockIdx.x * blockDim.x + threadIdx.x;
    if (i < 256 * 384) {              // W1t[j][t], t = k*128+f
        int j = i / 384, t = i % 384;
        int k = t / 128, f = t % 128;
        g_W1t[i] = __float2half(W1[(f * 3 + k) * 256 + j]);
    }
    if (i < 128 * 256) {              // W2catT[j][f]
        int j = i / 256, f = i % 256;
        int kk = (j < 64) ? 1 : 2;
        int jj = (j < 64) ? j : (j - 64);
        g_W2catT[i] = __float2half(W2[(f * 3 + kk) * 64 + jj]);
    }
    if (i < 64 * 256) {               // W2dT[j][f] = W2_0 - W2_2
        int j = i / 256, f = i % 256;
        g_W2dT[i] = __float2half(W2[(f * 3 + 0) * 64 + j] - W2[(f * 3 + 2) * 64 + j]);
    }
    if (i < NIDX) g_mark[idx[i]] = 1;
}

// ---------------- SpMM over the fp16 basis buffer (8-edge unroll) ----------------
template <bool SUB>
__global__ void spmm_bh_kernel(int src_off, int dst_off) {
    int gw = (blockIdx.x * blockDim.x + threadIdx.x) >> 5;
    if (gw >= NN) return;
    int lane = threadIdx.x & 31;
    int s = g_row_ptr[gw], e = g_row_ptr[gw + 1];

    float4 acc = make_float4(0.f, 0.f, 0.f, 0.f);
    int i = s;
    for (; i + 7 < e; i += 8) {
        int2 ev[8];
        uint2 u[8];
        #pragma unroll
        for (int q = 0; q < 8; q++) ev[q] = g_csr[i + q];
        #pragma unroll
        for (int q = 0; q < 8; q++)
            u[q] = *reinterpret_cast<const uint2*>(
                g_Bh + (size_t)ev[q].x * 384 + src_off + lane * 4);
        #pragma unroll
        for (int q = 0; q < 8; q++) {
            float v = __int_as_float(ev[q].y);
            float4 f = h4_to_f4(u[q]);
            acc.x += v * f.x; acc.y += v * f.y;
            acc.z += v * f.z; acc.w += v * f.w;
        }
    }
    for (; i < e; i++) {
        int2 ev = g_csr[i];
        float v = __int_as_float(ev.y);
        uint2 u = *reinterpret_cast<const uint2*>(
            g_Bh + (size_t)ev.x * 384 + src_off + lane * 4);
        float4 f = h4_to_f4(u);
        acc.x += v * f.x; acc.y += v * f.y;
        acc.z += v * f.z; acc.w += v * f.w;
    }

    if (SUB) {
        uint2 su = *reinterpret_cast<const uint2*>(
            g_Bh + (size_t)gw * 384 + lane * 4);
        float4 sv = h4_to_f4(su);
        acc.x = 2.f * acc.x - sv.x;
        acc.y = 2.f * acc.y - sv.y;
        acc.z = 2.f * acc.z - sv.z;
        acc.w = 2.f * acc.w - sv.w;
    }
    *reinterpret_cast<uint2*>(g_Bh + (size_t)gw * 384 + dst_off + lane * 4) =
        f4_to_h4(acc);
}

// ---------------- LV = L @ V  (V = Zh cols 64:128), fp16 64-wide -----------------
__global__ void spmm_lv_kernel() {
    int gw = (blockIdx.x * blockDim.x + threadIdx.x) >> 5;
    if (gw >= NN) return;
    int lane = threadIdx.x & 31;
    int s = g_row_ptr[gw], e = g_row_ptr[gw + 1];

    float2 acc = make_float2(0.f, 0.f);
    int i = s;
    for (; i + 7 < e; i += 8) {
        int2 ev[8];
        __half2 h[8];
        #pragma unroll
        for (int q = 0; q < 8; q++) ev[q] = g_csr[i + q];
        #pragma unroll
        for (int q = 0; q < 8; q++)
            h[q] = *reinterpret_cast<const __half2*>(
                g_Zh + (size_t)ev[q].x * 128 + 64 + lane * 2);
        #pragma unroll
        for (int q = 0; q < 8; q++) {
            float v = __int_as_float(ev[q].y);
            float2 f = __half22float2(h[q]);
            acc.x += v * f.x; acc.y += v * f.y;
        }
    }
    for (; i < e; i++) {
        int2 ev = g_csr[i];
        float v = __int_as_float(ev.y);
        __half2 h = *reinterpret_cast<const __half2*>(
            g_Zh + (size_t)ev.x * 128 + 64 + lane * 2);
        float2 f = __half22float2(h);
        acc.x += v * f.x; acc.y += v * f.y;
    }
    *reinterpret_cast<__half2*>(g_LVh + (size_t)gw * 64 + lane * 2) =
        __floats2half2_rn(acc.x, acc.y);
}

// ---------------- final: marked rows, P[r] += LU[r] + 2*(L LV)[r]; clear mark ----
__global__ void final_rows_kernel() {
    int gw = (blockIdx.x * blockDim.x + threadIdx.x) >> 5;
    if (gw >= NN) return;
    if (g_mark[gw] == 0) return;
    int lane = threadIdx.x & 31;
    int s = g_row_ptr[gw], e = g_row_ptr[gw + 1];

    float2 aU = make_float2(0.f, 0.f);
    float2 aL = make_float2(0.f, 0.f);
    int i = s;
    for (; i + 3 < e; i += 4) {
        #pragma unroll
        for (int q = 0; q < 4; q++) {
            int2 ev = g_csr[i + q];
            float v = __int_as_float(ev.y);
            __half2 hu = *reinterpret_cast<const __half2*>(
                g_Zh + (size_t)ev.x * 128 + lane * 2);
            __half2 hl = *reinterpret_cast<const __half2*>(
                g_LVh + (size_t)ev.x * 64 + lane * 2);
            float2 fu = __half22float2(hu);
            float2 fl = __half22float2(hl);
            aU.x += v * fu.x; aU.y += v * fu.y;
            aL.x += v * fl.x; aL.y += v * fl.y;
        }
    }
    for (; i < e; i++) {
        int2 ev = g_csr[i];
        float v = __int_as_float(ev.y);
        __half2 hu = *reinterpret_cast<const __half2*>(
            g_Zh + (size_t)ev.x * 128 + lane * 2);
        __half2 hl = *reinterpret_cast<const __half2*>(
            g_LVh + (size_t)ev.x * 64 + lane * 2);
        float2 fu = __half22float2(hu);
        float2 fl = __half22float2(hl);
        aU.x += v * fu.x; aU.y += v * fu.y;
        aL.x += v * fl.x; aL.y += v * fl.y;
    }

    float2* pr = reinterpret_cast<float2*>(g_P + (size_t)gw * 64) + lane;
    float2 p = *pr;
    p.x += aU.x + 2.f * aL.x;
    p.y += aU.y + 2.f * aL.y;
    *pr = p;
    if (lane == 0) g_mark[gw] = 0;   // self-clean for next call
}

__global__ void gather_out_kernel(const int* __restrict__ idx,
                                  float* __restrict__ out) {
    int i = blockIdx.x * blockDim.x + threadIdx.x;  // NIDX*16 float4
    if (i >= NIDX * 16) return;
    int n = i >> 4, f4 = i & 15;
    int r = idx[n];
    reinterpret_cast<float4*>(out + (size_t)n * 64)[f4] =
        reinterpret_cast<const float4*>(g_P + (size_t)r * 64)[f4];
}

// ---------------- fp16 tensor-core GEMM (mma.m16n8k16, fp32 accum) ---------------
// A: fp16 [M][lda] row-major.  B: fp16 [Ntot][ldb] n-major (K contiguous).
template <int BM, int BN, int BK, int WM, int WN, bool RELU, bool ADD_BIAS, bool HALF_OUT>
__global__ __launch_bounds__((BM / WM) * (BN / WN) * 32)
void gemm_f16_kernel(const __half* __restrict__ A, int lda,
                     const __half* __restrict__ B, int ldb,
                     const float* __restrict__ bias,
                     void* __restrict__ Cv, int ldc,
                     int M, int Ktot) {
    constexpr int WARPS_M = BM / WM;
    constexpr int WARPS_N = BN / WN;
    constexpr int THREADS = WARPS_M * WARPS_N * 32;
    constexpr int MT = WM / 16;
    constexpr int NT = WN / 8;
    constexpr int LDS = BK + 8;
    constexpr int HP = BK / 4;              // uint2 groups per row
    constexpr int A_IT = BM * HP / THREADS;
    constexpr int B_IT = BN * HP / THREADS;

    __shared__ __half As[BM][LDS];
    __shared__ __half Bs[BN][LDS];

    int tid = threadIdx.x;
    int lane = tid & 31, wid = tid >> 5;
    int gid = lane >> 2;
    int tig2 = (lane & 3) * 2;
    int wm = (wid / WARPS_N) * WM;
    int wn = (wid % WARPS_N) * WN;
    int m0 = blockIdx.y * BM;
    int n0 = blockIdx.x * BN;

    float acc[MT][NT][4];
    #pragma unroll
    for (int mt = 0; mt < MT; mt++)
        #pragma unroll
        for (int nt = 0; nt < NT; nt++)
            #pragma unroll
            for (int q = 0; q < 4; q++) acc[mt][nt][q] = 0.f;

    for (int k0 = 0; k0 < Ktot; k0 += BK) {
        #pragma unroll
        for (int it = 0; it < A_IT; it++) {
            int g = tid + it * THREADS;
            int r = g / HP, c = (g % HP) * 4;
            int m = m0 + r;
            uint2 v = make_uint2(0u, 0u);
            if (m < M)
                v = *reinterpret_cast<const uint2*>(A + (size_t)m * lda + k0 + c);
            *reinterpret_cast<uint2*>(&As[r][c]) = v;
        }
        #pragma unroll
        for (int it = 0; it < B_IT; it++) {
            int g = tid + it * THREADS;
            int r = g / HP, c = (g % HP) * 4;
            *reinterpret_cast<uint2*>(&Bs[r][c]) =
                *reinterpret_cast<const uint2*>(B + (size_t)(n0 + r) * ldb + k0 + c);
        }
        __syncthreads();
        #pragma unroll
        for (int kk = 0; kk < BK; kk += 16) {
            uint32_t af[MT][4], bf[NT][2];
            #pragma unroll
            for (int mt = 0; mt < MT; mt++) {
                int r = wm + mt * 16 + gid;
                af[mt][0] = *reinterpret_cast<const uint32_t*>(&As[r][kk + tig2]);
                af[mt][1] = *reinterpret_cast<const uint32_t*>(&As[r + 8][kk + tig2]);
                af[mt][2] = *reinterpret_cast<const uint32_t*>(&As[r][kk + tig2 + 8]);
                af[mt][3] = *reinterpret_cast<const uint32_t*>(&As[r + 8][kk + tig2 + 8]);
            }
            #pragma unroll
            for (int nt = 0; nt < NT; nt++) {
                int n = wn + nt * 8 + gid;
                bf[nt][0] = *reinterpret_cast<const uint32_t*>(&Bs[n][kk + tig2]);
                bf[nt][1] = *reinterpret_cast<const uint32_t*>(&Bs[n][kk + tig2 + 8]);
            }
            #pragma unroll
            for (int mt = 0; mt < MT; mt++)
                #pragma unroll
                for (int nt = 0; nt < NT; nt++)
                    asm volatile(
                        "mma.sync.aligned.m16n8k16.row.col.f32.f16.f16.f32 "
                        "{%0,%1,%2,%3}, {%4,%5,%6,%7}, {%8,%9}, {%0,%1,%2,%3};"
                        : "+f"(acc[mt][nt][0]), "+f"(acc[mt][nt][1]),
                          "+f"(acc[mt][nt][2]), "+f"(acc[mt][nt][3])
                        : "r"(af[mt][0]), "r"(af[mt][1]), "r"(af[mt][2]), "r"(af[mt][3]),
                          "r"(bf[nt][0]), "r"(bf[nt][1]));
        }
        __syncthreads();
    }

    #pragma unroll
    for (int mt = 0; mt < MT; mt++) {
        int r0 = m0 + wm + mt * 16 + gid;
        #pragma unroll
        for (int nt = 0; nt < NT; nt++) {
            int n = n0 + wn + nt * 8 + tig2;
            float bx = 0.f, by = 0.f;
            if (ADD_BIAS) { bx = bias[n]; by = bias[n + 1]; }
            float2 o0, o1;
            o0.x = acc[mt][nt][0] + bx; o0.y = acc[mt][nt][1] + by;
            o1.x = acc[mt][nt][2] + bx; o1.y = acc[mt][nt][3] + by;
            if (RELU) {
                o0.x = fmaxf(o0.x, 0.f); o0.y = fmaxf(o0.y, 0.f);
                o1.x = fmaxf(o1.x, 0.f); o1.y = fmaxf(o1.y, 0.f);
            }
            if (HALF_OUT) {
                __half* C = (__half*)Cv;
                if (r0 < M)
                    *reinterpret_cast<__half2*>(C + (size_t)r0 * ldc + n) =
                        __floats2half2_rn(o0.x, o0.y);
                if (r0 + 8 < M)
                    *reinterpret_cast<__half2*>(C + (size_t)(r0 + 8) * ldc + n) =
                        __floats2half2_rn(o1.x, o1.y);
            } else {
                float* C = (float*)Cv;
                if (r0 < M)
                    *reinterpret_cast<float2*>(C + (size_t)r0 * ldc + n) = o0;
                if (r0 + 8 < M)
                    *reinterpret_cast<float2*>(C + (size_t)(r0 + 8) * ldc + n) = o1;
            }
        }
    }
}

// ---------------- launch ----------------------------------------------------------
extern "C" void kernel_launch(void* const* d_in, const int* in_sizes, int n_in,
                              void* d_out, int out_size) {
    const float* x    = (const float*)d_in[0];
    const float* vals = (const float*)d_in[1];
    const float* W1   = (const float*)d_in[2];
    const float* b1   = (const float*)d_in[3];
    const float* W2   = (const float*)d_in[4];
    const float* b2   = (const float*)d_in[5];
    const int*   rows = (const int*)d_in[6];
    const int*   cols = (const int*)d_in[7];
    const int*   idx  = (const int*)d_in[8];
    float*       out  = (float*)d_out;

    float  *p;
    __half *bh, *hh, *zh, *w1t, *w2catT, *w2dT;
    cudaGetSymbolAddress((void**)&p,      g_P);
    cudaGetSymbolAddress((void**)&bh,     g_Bh);
    cudaGetSymbolAddress((void**)&hh,     g_Hh);
    cudaGetSymbolAddress((void**)&zh,     g_Zh);
    cudaGetSymbolAddress((void**)&w1t,    g_W1t);
    cudaGetSymbolAddress((void**)&w2catT, g_W2catT);
    cudaGetSymbolAddress((void**)&w2dT,   g_W2dT);

    int warp_blocks = cdiv(NN * 32, 256);

    // 0-2: CSR build (g_count pre-zeroed; scan re-zeroes it) + x->fp16 copy
    hist_kernel<<<cdiv(NNZE, 256), 256>>>(rows);
    scan_kernel<<<1, 1024>>>();
    scatter_copyx_kernel<<<cdiv(NNZE, 256), 256>>>(rows, cols, vals, x);
    // 3: T1 = L x   (profiled launch)
    spmm_bh_kernel<false><<<warp_blocks, 256>>>(0, 128);
    // 4: T2 = 2 L T1 - x
    spmm_bh_kernel<true><<<warp_blocks, 256>>>(128, 256);
    // 5: weights -> fp16 transposed + mark output rows
    prep_w_kernel<<<cdiv(256 * 384, 256), 256>>>(W1, W2, idx);

    // 6: H = relu(Basis @ W1 + b1) -> fp16
    {
        dim3 grid(2, cdiv(NN, 128));
        gemm_f16_kernel<128, 128, 32, 32, 64, true, true, true><<<grid, 256>>>(
            bh, 384, w1t, 384, b1, hh, 256, NN, 384);
    }
    // 7: Z = H @ [W2_1 | W2_2] -> fp16
    {
        dim3 grid(1, cdiv(NN, 128));
        gemm_f16_kernel<128, 128, 32, 32, 64, false, false, true><<<grid, 256>>>(
            hh, 256, w2catT, 256, nullptr, zh, 128, NN, 256);
    }
    // 8: P = H @ (W2_0 - W2_2) + b2 -> fp32
    {
        dim3 grid(1, cdiv(NN, 128));
        gemm_f16_kernel<128, 64, 32, 32, 32, false, true, false><<<grid, 256>>>(
            hh, 256, w2dT, 256, b2, p, 64, NN, 256);
    }

    // 9: LV = L @ V
    spmm_lv_kernel<<<warp_blocks, 256>>>();
    // 10: marked rows: P[r] += LU[r] + 2*(L LV)[r]  (clears marks)
    final_rows_kernel<<<warp_blocks, 256>>>();
    // 11: out[i] = P[idx[i]]
    gather_out_kernel<<<cdiv(NIDX * 16, 256), 256>>>(idx, out);
}

// round 12
// speedup vs baseline: 1.4550x; 1.0788x over previous
#include <cuda_runtime.h>
#include <cuda_fp16.h>
#include <cstdint>

#define NN   100000
#define NNZE 3200000
#define NIDX 50000
#define BKT  128          // bucket capacity per row (max degree ~60)

static inline int cdiv(int a, int b) { return (a + b - 1) / b; }

// ---------------- scratch (device globals; zero-initialized at module load) ----
__device__ int    g_cursor[NN];     // degree counters; cleared at end of launch
__device__ int    g_mark[NN];       // set by prep_w, cleared by final_rows
__device__ int4   g_bkt4[(size_t)NN * (BKT / 2)];   // 2 edges per int4
// fp16 basis: [N][384] = [x | T1 | T2]
__device__ __half g_Bh[(size_t)NN * 384];
// fp16 hidden: [N][256]
__device__ __half g_Hh[(size_t)NN * 256];
// fp16 Z: [N][128]  ([0:64)=U, [64:128)=V)
__device__ __half g_Zh[(size_t)NN * 128];
// fp16 Q = U + 2*(L V): [N][64]
__device__ __half g_Qh[(size_t)NN * 64];
// P = H @ (W2_0 - W2_2) + b2, fp32; final pass accumulates in place
__device__ float  g_P[(size_t)NN * 64];
// fp16 transposed weights (n-major, K contiguous)
__device__ __half g_W1t[256 * 384];
__device__ __half g_W2catT[128 * 256];
__device__ __half g_W2dT[64 * 256];

// ---------------- helpers -------------------------------------------------------
__device__ __forceinline__ float4 h4_to_f4(uint2 u) {
    __half2 h0 = *reinterpret_cast<__half2*>(&u.x);
    __half2 h1 = *reinterpret_cast<__half2*>(&u.y);
    float2 a = __half22float2(h0);
    float2 b = __half22float2(h1);
    return make_float4(a.x, a.y, b.x, b.y);
}
__device__ __forceinline__ uint2 f4_to_h4(float4 v) {
    __half2 h0 = __floats2half2_rn(v.x, v.y);
    __half2 h1 = __floats2half2_rn(v.z, v.w);
    uint2 u;
    u.x = *reinterpret_cast<uint32_t*>(&h0);
    u.y = *reinterpret_cast<uint32_t*>(&h1);
    return u;
}

// ---------------- weight prep + output-row marking -------------------------------
__global__ void prep_w_kernel(const float* __restrict__ W1,
                              const float* __restrict__ W2,
                              const int* __restrict__ idx) {
    int i = blockIdx.x * blockDim.x + threadIdx.x;
    if (i < 256 * 384) {              // W1t[j][t], t = k*128+f
        int j = i / 384, t = i % 384;
        int k = t / 128, f = t % 128;
        g_W1t[i] = __float2half(W1[(f * 3 + k) * 256 + j]);
    }
    if (i < 128 * 256) {              // W2catT[j][f]
        int j = i / 256, f = i % 256;
        int kk = (j < 64) ? 1 : 2;
        int jj = (j < 64) ? j : (j - 64);
        g_W2catT[i] = __float2half(W2[(f * 3 + kk) * 64 + jj]);
    }
    if (i < 64 * 256) {               // W2dT[j][f] = W2_0 - W2_2
        int j = i / 256, f = i % 256;
        g_W2dT[i] = __float2half(W2[(f * 3 + 0) * 64 + j] - W2[(f * 3 + 2) * 64 + j]);
    }
    if (i < NIDX) g_mark[idx[i]] = 1;
}

// ---------------- bucket-CSR scatter + x -> fp16 copy ----------------------------
__global__ void scatter_copyx_kernel(const int* __restrict__ rows,
                                     const int* __restrict__ cols,
                                     const float* __restrict__ vals,
                                     const float* __restrict__ x) {
    int i = blockIdx.x * blockDim.x + threadIdx.x;
    if (i < NNZE) {
        int r = rows[i];
        int pos = atomicAdd(&g_cursor[r], 1);
        reinterpret_cast<int2*>(g_bkt4)[(size_t)r * BKT + pos] =
            make_int2(cols[i], __float_as_int(vals[i]));
    }
    if (i < NN * 32) {
        int n = i >> 5, f4 = i & 31;
        float4 v = reinterpret_cast<const float4*>(x)[i];
        reinterpret_cast<uint2*>(g_Bh + (size_t)n * 384)[f4] = f4_to_h4(v);
    }
}

// ---------------- SpMM over fp16 basis (8-edge unroll, paired csr loads) ---------
template <bool SUB>
__global__ void spmm_bh_kernel(int src_off, int dst_off) {
    int gw = (blockIdx.x * blockDim.x + threadIdx.x) >> 5;
    if (gw >= NN) return;
    int lane = threadIdx.x & 31;
    int n = g_cursor[gw];
    const int4* b4 = g_bkt4 + (size_t)gw * (BKT / 2);
    const int2* b2 = reinterpret_cast<const int2*>(b4);

    float4 acc = make_float4(0.f, 0.f, 0.f, 0.f);
    int i = 0;
    for (; i + 8 <= n; i += 8) {
        int4 e4[4];
        #pragma unroll
        for (int q = 0; q < 4; q++) e4[q] = b4[(i >> 1) + q];
        uint2 u[8];
        #pragma unroll
        for (int q = 0; q < 4; q++) {
            u[2*q]   = *reinterpret_cast<const uint2*>(
                g_Bh + (size_t)e4[q].x * 384 + src_off + lane * 4);
            u[2*q+1] = *reinterpret_cast<const uint2*>(
                g_Bh + (size_t)e4[q].z * 384 + src_off + lane * 4);
        }
        #pragma unroll
        for (int q = 0; q < 4; q++) {
            float v0 = __int_as_float(e4[q].y);
            float v1 = __int_as_float(e4[q].w);
            float4 f0 = h4_to_f4(u[2*q]);
            float4 f1 = h4_to_f4(u[2*q+1]);
            acc.x += v0 * f0.x + v1 * f1.x;
            acc.y += v0 * f0.y + v1 * f1.y;
            acc.z += v0 * f0.z + v1 * f1.z;
            acc.w += v0 * f0.w + v1 * f1.w;
        }
    }
    for (; i < n; i++) {
        int2 ev = b2[i];
        float v = __int_as_float(ev.y);
        uint2 u = *reinterpret_cast<const uint2*>(
            g_Bh + (size_t)ev.x * 384 + src_off + lane * 4);
        float4 f = h4_to_f4(u);
        acc.x += v * f.x; acc.y += v * f.y;
        acc.z += v * f.z; acc.w += v * f.w;
    }

    if (SUB) {
        uint2 su = *reinterpret_cast<const uint2*>(
            g_Bh + (size_t)gw * 384 + lane * 4);
        float4 sv = h4_to_f4(su);
        acc.x = 2.f * acc.x - sv.x;
        acc.y = 2.f * acc.y - sv.y;
        acc.z = 2.f * acc.z - sv.z;
        acc.w = 2.f * acc.w - sv.w;
    }
    *reinterpret_cast<uint2*>(g_Bh + (size_t)gw * 384 + dst_off + lane * 4) =
        f4_to_h4(acc);
}

// ---------------- Q = U + 2 * (L @ V), fp16 64-wide ------------------------------
__global__ void spmm_q_kernel() {
    int gw = (blockIdx.x * blockDim.x + threadIdx.x) >> 5;
    if (gw >= NN) return;
    int lane = threadIdx.x & 31;
    int n = g_cursor[gw];
    const int4* b4 = g_bkt4 + (size_t)gw * (BKT / 2);
    const int2* b2 = reinterpret_cast<const int2*>(b4);

    float2 acc = make_float2(0.f, 0.f);
    int i = 0;
    for (; i + 8 <= n; i += 8) {
        int4 e4[4];
        #pragma unroll
        for (int q = 0; q < 4; q++) e4[q] = b4[(i >> 1) + q];
        __half2 h[8];
        #pragma unroll
        for (int q = 0; q < 4; q++) {
            h[2*q]   = *reinterpret_cast<const __half2*>(
                g_Zh + (size_t)e4[q].x * 128 + 64 + lane * 2);
            h[2*q+1] = *reinterpret_cast<const __half2*>(
                g_Zh + (size_t)e4[q].z * 128 + 64 + lane * 2);
        }
        #pragma unroll
        for (int q = 0; q < 4; q++) {
            float v0 = __int_as_float(e4[q].y);
            float v1 = __int_as_float(e4[q].w);
            float2 f0 = __half22float2(h[2*q]);
            float2 f1 = __half22float2(h[2*q+1]);
            acc.x += v0 * f0.x + v1 * f1.x;
            acc.y += v0 * f0.y + v1 * f1.y;
        }
    }
    for (; i < n; i++) {
        int2 ev = b2[i];
        float v = __int_as_float(ev.y);
        __half2 h = *reinterpret_cast<const __half2*>(
            g_Zh + (size_t)ev.x * 128 + 64 + lane * 2);
        float2 f = __half22float2(h);
        acc.x += v * f.x; acc.y += v * f.y;
    }
    // Q[r] = U[r] + 2 * acc
    __half2 uh = *reinterpret_cast<const __half2*>(g_Zh + (size_t)gw * 128 + lane * 2);
    float2 uf = __half22float2(uh);
    *reinterpret_cast<__half2*>(g_Qh + (size_t)gw * 64 + lane * 2) =
        __floats2half2_rn(uf.x + 2.f * acc.x, uf.y + 2.f * acc.y);
}

// ---------------- final: marked rows, P[r] += sum v * Q[col]; clear mark ----------
__global__ void final_rows_kernel() {
    int gw = (blockIdx.x * blockDim.x + threadIdx.x) >> 5;
    if (gw >= NN) return;
    if (g_mark[gw] == 0) return;
    int lane = threadIdx.x & 31;
    int n = g_cursor[gw];
    const int4* b4 = g_bkt4 + (size_t)gw * (BKT / 2);
    const int2* b2 = reinterpret_cast<const int2*>(b4);

    float2 acc = make_float2(0.f, 0.f);
    int i = 0;
    for (; i + 4 <= n; i += 4) {
        int4 e4[2];
        #pragma unroll
        for (int q = 0; q < 2; q++) e4[q] = b4[(i >> 1) + q];
        __half2 h[4];
        #pragma unroll
        for (int q = 0; q < 2; q++) {
            h[2*q]   = *reinterpret_cast<const __half2*>(
                g_Qh + (size_t)e4[q].x * 64 + lane * 2);
            h[2*q+1] = *reinterpret_cast<const __half2*>(
                g_Qh + (size_t)e4[q].z * 64 + lane * 2);
        }
        #pragma unroll
        for (int q = 0; q < 2; q++) {
            float v0 = __int_as_float(e4[q].y);
            float v1 = __int_as_float(e4[q].w);
            float2 f0 = __half22float2(h[2*q]);
            float2 f1 = __half22float2(h[2*q+1]);
            acc.x += v0 * f0.x + v1 * f1.x;
            acc.y += v0 * f0.y + v1 * f1.y;
        }
    }
    for (; i < n; i++) {
        int2 ev = b2[i];
        float v = __int_as_float(ev.y);
        __half2 h = *reinterpret_cast<const __half2*>(
            g_Qh + (size_t)ev.x * 64 + lane * 2);
        float2 f = __half22float2(h);
        acc.x += v * f.x; acc.y += v * f.y;
    }

    float2* pr = reinterpret_cast<float2*>(g_P + (size_t)gw * 64) + lane;
    float2 p = *pr;
    p.x += acc.x;
    p.y += acc.y;
    *pr = p;
    if (lane == 0) g_mark[gw] = 0;   // self-clean
}

// ---------------- output gather + cursor cleanup ----------------------------------
__global__ void gather_out_kernel(const int* __restrict__ idx,
                                  float* __restrict__ out) {
    int i = blockIdx.x * blockDim.x + threadIdx.x;
    if (i < NN) g_cursor[i] = 0;           // self-clean for next launch
    if (i >= NIDX * 16) return;
    int n = i >> 4, f4 = i & 15;
    int r = idx[n];
    reinterpret_cast<float4*>(out + (size_t)n * 64)[f4] =
        reinterpret_cast<const float4*>(g_P + (size_t)r * 64)[f4];
}

// ---------------- fp16 tensor-core GEMM (mma.m16n8k16, fp32 accum) ----------------
template <int BM, int BN, int BK, int WM, int WN, bool RELU, bool ADD_BIAS, bool HALF_OUT>
__global__ __launch_bounds__((BM / WM) * (BN / WN) * 32)
void gemm_f16_kernel(const __half* __restrict__ A, int lda,
                     const __half* __restrict__ B, int ldb,
                     const float* __restrict__ bias,
                     void* __restrict__ Cv, int ldc,
                     int M, int Ktot) {
    constexpr int WARPS_M = BM / WM;
    constexpr int WARPS_N = BN / WN;
    constexpr int THREADS = WARPS_M * WARPS_N * 32;
    constexpr int MT = WM / 16;
    constexpr int NT = WN / 8;
    constexpr int LDS = BK + 8;
    constexpr int HP = BK / 4;
    constexpr int A_IT = BM * HP / THREADS;
    constexpr int B_IT = BN * HP / THREADS;

    __shared__ __half As[BM][LDS];
    __shared__ __half Bs[BN][LDS];

    int tid = threadIdx.x;
    int lane = tid & 31, wid = tid >> 5;
    int gid = lane >> 2;
    int tig2 = (lane & 3) * 2;
    int wm = (wid / WARPS_N) * WM;
    int wn = (wid % WARPS_N) * WN;
    int m0 = blockIdx.y * BM;
    int n0 = blockIdx.x * BN;

    float acc[MT][NT][4];
    #pragma unroll
    for (int mt = 0; mt < MT; mt++)
        #pragma unroll
        for (int nt = 0; nt < NT; nt++)
            #pragma unroll
            for (int q = 0; q < 4; q++) acc[mt][nt][q] = 0.f;

    for (int k0 = 0; k0 < Ktot; k0 += BK) {
        #pragma unroll
        for (int it = 0; it < A_IT; it++) {
            int g = tid + it * THREADS;
            int r = g / HP, c = (g % HP) * 4;
            int m = m0 + r;
            uint2 v = make_uint2(0u, 0u);
            if (m < M)
                v = *reinterpret_cast<const uint2*>(A + (size_t)m * lda + k0 + c);
            *reinterpret_cast<uint2*>(&As[r][c]) = v;
        }
        #pragma unroll
        for (int it = 0; it < B_IT; it++) {
            int g = tid + it * THREADS;
            int r = g / HP, c = (g % HP) * 4;
            *reinterpret_cast<uint2*>(&Bs[r][c]) =
                *reinterpret_cast<const uint2*>(B + (size_t)(n0 + r) * ldb + k0 + c);
        }
        __syncthreads();
        #pragma unroll
        for (int kk = 0; kk < BK; kk += 16) {
            uint32_t af[MT][4], bf[NT][2];
            #pragma unroll
            for (int mt = 0; mt < MT; mt++) {
                int r = wm + mt * 16 + gid;
                af[mt][0] = *reinterpret_cast<const uint32_t*>(&As[r][kk + tig2]);
                af[mt][1] = *reinterpret_cast<const uint32_t*>(&As[r + 8][kk + tig2]);
                af[mt][2] = *reinterpret_cast<const uint32_t*>(&As[r][kk + tig2 + 8]);
                af[mt][3] = *reinterpret_cast<const uint32_t*>(&As[r + 8][kk + tig2 + 8]);
            }
            #pragma unroll
            for (int nt = 0; nt < NT; nt++) {
                int n = wn + nt * 8 + gid;
                bf[nt][0] = *reinterpret_cast<const uint32_t*>(&Bs[n][kk + tig2]);
                bf[nt][1] = *reinterpret_cast<const uint32_t*>(&Bs[n][kk + tig2 + 8]);
            }
            #pragma unroll
            for (int mt = 0; mt < MT; mt++)
                #pragma unroll
                for (int nt = 0; nt < NT; nt++)
                    asm volatile(
                        "mma.sync.aligned.m16n8k16.row.col.f32.f16.f16.f32 "
                        "{%0,%1,%2,%3}, {%4,%5,%6,%7}, {%8,%9}, {%0,%1,%2,%3};"
                        : "+f"(acc[mt][nt][0]), "+f"(acc[mt][nt][1]),
                          "+f"(acc[mt][nt][2]), "+f"(acc[mt][nt][3])
                        : "r"(af[mt][0]), "r"(af[mt][1]), "r"(af[mt][2]), "r"(af[mt][3]),
                          "r"(bf[nt][0]), "r"(bf[nt][1]));
        }
        __syncthreads();
    }

    #pragma unroll
    for (int mt = 0; mt < MT; mt++) {
        int r0 = m0 + wm + mt * 16 + gid;
        #pragma unroll
        for (int nt = 0; nt < NT; nt++) {
            int n = n0 + wn + nt * 8 + tig2;
            float bx = 0.f, by = 0.f;
            if (ADD_BIAS) { bx = bias[n]; by = bias[n + 1]; }
            float2 o0, o1;
            o0.x = acc[mt][nt][0] + bx; o0.y = acc[mt][nt][1] + by;
            o1.x = acc[mt][nt][2] + bx; o1.y = acc[mt][nt][3] + by;
            if (RELU) {
                o0.x = fmaxf(o0.x, 0.f); o0.y = fmaxf(o0.y, 0.f);
                o1.x = fmaxf(o1.x, 0.f); o1.y = fmaxf(o1.y, 0.f);
            }
            if (HALF_OUT) {
                __half* C = (__half*)Cv;
                if (r0 < M)
                    *reinterpret_cast<__half2*>(C + (size_t)r0 * ldc + n) =
                        __floats2half2_rn(o0.x, o0.y);
                if (r0 + 8 < M)
                    *reinterpret_cast<__half2*>(C + (size_t)(r0 + 8) * ldc + n) =
                        __floats2half2_rn(o1.x, o1.y);
            } else {
                float* C = (float*)Cv;
                if (r0 < M)
                    *reinterpret_cast<float2*>(C + (size_t)r0 * ldc + n) = o0;
                if (r0 + 8 < M)
                    *reinterpret_cast<float2*>(C + (size_t)(r0 + 8) * ldc + n) = o1;
            }
        }
    }
}

// ---------------- launch ------------------------------------------------------------
extern "C" void kernel_launch(void* const* d_in, const int* in_sizes, int n_in,
                              void* d_out, int out_size) {
    const float* x    = (const float*)d_in[0];
    const float* vals = (const float*)d_in[1];
    const float* W1   = (const float*)d_in[2];
    const float* b1   = (const float*)d_in[3];
    const float* W2   = (const float*)d_in[4];
    const float* b2   = (const float*)d_in[5];
    const int*   rows = (const int*)d_in[6];
    const int*   cols = (const int*)d_in[7];
    const int*   idx  = (const int*)d_in[8];
    float*       out  = (float*)d_out;

    float  *p;
    __half *bh, *hh, *zh, *w1t, *w2catT, *w2dT;
    cudaGetSymbolAddress((void**)&p,      g_P);
    cudaGetSymbolAddress((void**)&bh,     g_Bh);
    cudaGetSymbolAddress((void**)&hh,     g_Hh);
    cudaGetSymbolAddress((void**)&zh,     g_Zh);
    cudaGetSymbolAddress((void**)&w1t,    g_W1t);
    cudaGetSymbolAddress((void**)&w2catT, g_W2catT);
    cudaGetSymbolAddress((void**)&w2dT,   g_W2dT);

    int warp_blocks = cdiv(NN * 32, 256);

    // 0: weights -> fp16 transposed + mark output rows
    prep_w_kernel<<<cdiv(256 * 384, 256), 256>>>(W1, W2, idx);
    // 1: bucket-CSR scatter (cursor starts zero) + x -> fp16 basis
    scatter_copyx_kernel<<<cdiv(NNZE, 256), 256>>>(rows, cols, vals, x);
    // 2: T1 = L x
    spmm_bh_kernel<false><<<warp_blocks, 256>>>(0, 128);
    // 3: T2 = 2 L T1 - x   (profiled launch)
    spmm_bh_kernel<true><<<warp_blocks, 256>>>(128, 256);

    // 4: H = relu(Basis @ W1 + b1) -> fp16
    {
        dim3 grid(2, cdiv(NN, 128));
        gemm_f16_kernel<128, 128, 32, 32, 64, true, true, true><<<grid, 256>>>(
            bh, 384, w1t, 384, b1, hh, 256, NN, 384);
    }
    // 5: Z = H @ [W2_1 | W2_2] -> fp16
    {
        dim3 grid(1, cdiv(NN, 128));
        gemm_f16_kernel<128, 128, 32, 32, 64, false, false, true><<<grid, 256>>>(
            hh, 256, w2catT, 256, nullptr, zh, 128, NN, 256);
    }
    // 6: P = H @ (W2_0 - W2_2) + b2 -> fp32
    {
        dim3 grid(1, cdiv(NN, 128));
        gemm_f16_kernel<128, 64, 32, 32, 32, false, true, false><<<grid, 256>>>(
            hh, 256, w2dT, 256, b2, p, 64, NN, 256);
    }

    // 7: Q = U + 2 * (L V)
    spmm_q_kernel<<<warp_blocks, 256>>>();
    // 8: marked rows: P[r] += sum v * Q[col]   (clears marks)
    final_rows_kernel<<<warp_blocks, 256>>>();
    // 9: out[i] = P[idx[i]]  (+ cursor cleanup)
    gather_out_kernel<<<cdiv(NIDX * 16, 256), 256>>>(idx, out);
}

// round 13
// speedup vs baseline: 1.4606x; 1.0039x over previous
#include <cuda_runtime.h>
#include <cuda_fp16.h>
#include <cstdint>

#define NN   100000
#define NNZE 3200000
#define NIDX 50000
#define BKT  128          // bucket capacity per row (max degree ~60)

static inline int cdiv(int a, int b) { return (a + b - 1) / b; }

// ---------------- scratch (device globals; zero-initialized at module load) ----
__device__ int    g_cursor[NN];     // degree counters; cleared in gather_out
__device__ int    g_mark[NN];       // set in scatter_prep, cleared by final_rows
__device__ int4   g_bkt4[(size_t)NN * (BKT / 2)];   // 2 edges per int4; unused = 0
// fp16 basis: [N][384] = [x | T1 | T2]
__device__ __half g_Bh[(size_t)NN * 384];
// fp16 hidden: [N][256]
__device__ __half g_Hh[(size_t)NN * 256];
// fp16 Z: [N][128]  ([0:64)=U, [64:128)=V)
__device__ __half g_Zh[(size_t)NN * 128];
// fp16 Q = U + 2*(L V): [N][64]
__device__ __half g_Qh[(size_t)NN * 64];
// P = H @ (W2_0 - W2_2) + b2, fp32; final pass accumulates in place
__device__ float  g_P[(size_t)NN * 64];
// fp16 transposed weights (n-major, K contiguous)
__device__ __half g_W1t[256 * 384];
__device__ __half g_W2catT[128 * 256];
__device__ __half g_W2dT[64 * 256];

// ---------------- packed f32x2 helpers ---------------------------------------
__device__ __forceinline__ unsigned long long pack2(float v) {
    unsigned long long r;
    asm("mov.b64 %0, {%1, %1};" : "=l"(r) : "f"(v));
    return r;
}
// half2 bits -> packed float2 (u64)
__device__ __forceinline__ unsigned long long h2f2(uint32_t h) {
    unsigned long long r;
    asm("{\n\t"
        ".reg .b16 l, h;\n\t"
        ".reg .f32 fl, fh;\n\t"
        "mov.b32 {l, h}, %1;\n\t"
        "cvt.f32.f16 fl, l;\n\t"
        "cvt.f32.f16 fh, h;\n\t"
        "mov.b64 %0, {fl, fh};\n\t"
        "}" : "=l"(r) : "r"(h));
    return r;
}
__device__ __forceinline__ void fma2(unsigned long long& acc,
                                     unsigned long long a, unsigned long long b) {
    asm("fma.rn.f32x2 %0, %1, %2, %0;" : "+l"(acc) : "l"(a), "l"(b));
}
__device__ __forceinline__ void add2(unsigned long long& a, unsigned long long b) {
    asm("add.rn.f32x2 %0, %0, %1;" : "+l"(a) : "l"(b));
}
__device__ __forceinline__ float2 unpack2(unsigned long long a) {
    float2 f;
    asm("mov.b64 {%0, %1}, %2;" : "=f"(f.x), "=f"(f.y) : "l"(a));
    return f;
}
__device__ __forceinline__ uint2 f4_to_h4(float4 v) {
    __half2 h0 = __floats2half2_rn(v.x, v.y);
    __half2 h1 = __floats2half2_rn(v.z, v.w);
    uint2 u;
    u.x = *reinterpret_cast<uint32_t*>(&h0);
    u.y = *reinterpret_cast<uint32_t*>(&h1);
    return u;
}

// ---------------- scatter + x->fp16 + weight prep + marking (one launch) -------
__global__ void scatter_prep_kernel(const int* __restrict__ rows,
                                    const int* __restrict__ cols,
                                    const float* __restrict__ vals,
                                    const float* __restrict__ x,
                                    const float* __restrict__ W1,
                                    const float* __restrict__ W2,
                                    const int* __restrict__ idx) {
    int i = blockIdx.x * blockDim.x + threadIdx.x;
    if (i < NNZE) {
        int r = rows[i];
        int pos = atomicAdd(&g_cursor[r], 1);
        reinterpret_cast<int2*>(g_bkt4)[(size_t)r * BKT + pos] =
            make_int2(cols[i], __float_as_int(vals[i]));
    }
    if (i < NN * 32) {
        int n = i >> 5, f4 = i & 31;
        float4 v = reinterpret_cast<const float4*>(x)[i];
        reinterpret_cast<uint2*>(g_Bh + (size_t)n * 384)[f4] = f4_to_h4(v);
    }
    if (i < 256 * 384) {              // W1t[j][t], t = k*128+f
        int j = i / 384, t = i % 384;
        int k = t / 128, f = t % 128;
        g_W1t[i] = __float2half(W1[(f * 3 + k) * 256 + j]);
    }
    if (i < 128 * 256) {              // W2catT[j][f]
        int j = i / 256, f = i % 256;
        int kk = (j < 64) ? 1 : 2;
        int jj = (j < 64) ? j : (j - 64);
        g_W2catT[i] = __float2half(W2[(f * 3 + kk) * 64 + jj]);
    }
    if (i < 64 * 256) {               // W2dT[j][f] = W2_0 - W2_2
        int j = i / 256, f = i % 256;
        g_W2dT[i] = __float2half(W2[(f * 3 + 0) * 64 + j] - W2[(f * 3 + 2) * 64 + j]);
    }
    if (i < NIDX) g_mark[idx[i]] = 1;
}

// ---------------- SpMM over fp16 basis: half-warp edge pairing -----------------
// Row = 128 halves (256B). Lanes 0-15: even edges, lanes 16-31: odd edges.
// Each lane covers 16B (8 halves). Buckets are zero-padded -> no tail loop.
template <bool SUB>
__global__ void spmm_bh_kernel(int src_off, int dst_off) {
    int gw = (blockIdx.x * blockDim.x + threadIdx.x) >> 5;
    if (gw >= NN) return;
    int lane = threadIdx.x & 31;
    int hi = lane >> 4;          // which edge of each pair
    int sub = lane & 15;         // 16B feature slice
    int n = g_cursor[gw];
    const int4* b4 = g_bkt4 + (size_t)gw * (BKT / 2);

    unsigned long long acc[4] = {0ull, 0ull, 0ull, 0ull};

    int iters = (n + 7) >> 3;    // 8 edges (4 int4) per iter; padding contributes 0
    for (int it = 0; it < iters; it++) {
        int4 e[4];
        #pragma unroll
        for (int q = 0; q < 4; q++) e[q] = b4[it * 4 + q];
        #pragma unroll
        for (int q = 0; q < 4; q++) {
            int col   = hi ? e[q].z : e[q].x;
            int vbits = hi ? e[q].w : e[q].y;
            uint4 u = *reinterpret_cast<const uint4*>(
                g_Bh + (size_t)col * 384 + src_off + sub * 8);
            unsigned long long v2 = pack2(__int_as_float(vbits));
            fma2(acc[0], h2f2(u.x), v2);
            fma2(acc[1], h2f2(u.y), v2);
            fma2(acc[2], h2f2(u.z), v2);
            fma2(acc[3], h2f2(u.w), v2);
        }
    }
    // combine even/odd partial sums
    #pragma unroll
    for (int q = 0; q < 4; q++) {
        unsigned long long o = __shfl_xor_sync(0xffffffffu, acc[q], 16);
        add2(acc[q], o);
    }
    if (hi == 0) {
        float f[8];
        #pragma unroll
        for (int q = 0; q < 4; q++) {
            float2 t = unpack2(acc[q]);
            f[2 * q] = t.x; f[2 * q + 1] = t.y;
        }
        if (SUB) {
            uint4 su = *reinterpret_cast<const uint4*>(
                g_Bh + (size_t)gw * 384 + sub * 8);
            const __half* sh = reinterpret_cast<const __half*>(&su);
            #pragma unroll
            for (int q = 0; q < 8; q++)
                f[q] = 2.f * f[q] - __half2float(sh[q]);
        }
        uint4 o;
        __half2 h0 = __floats2half2_rn(f[0], f[1]);
        __half2 h1 = __floats2half2_rn(f[2], f[3]);
        __half2 h2 = __floats2half2_rn(f[4], f[5]);
        __half2 h3 = __floats2half2_rn(f[6], f[7]);
        o.x = *reinterpret_cast<uint32_t*>(&h0);
        o.y = *reinterpret_cast<uint32_t*>(&h1);
        o.z = *reinterpret_cast<uint32_t*>(&h2);
        o.w = *reinterpret_cast<uint32_t*>(&h3);
        *reinterpret_cast<uint4*>(g_Bh + (size_t)gw * 384 + dst_off + sub * 8) = o;
    }
}

// ---------------- Q = U + 2*(L V): rows 64 halves (128B), paired edges ---------
__global__ void spmm_q_kernel() {
    int gw = (blockIdx.x * blockDim.x + threadIdx.x) >> 5;
    if (gw >= NN) return;
    int lane = threadIdx.x & 31;
    int hi = lane >> 4;
    int sub = lane & 15;         // 8B slice (4 halves)
    int n = g_cursor[gw];
    const int4* b4 = g_bkt4 + (size_t)gw * (BKT / 2);

    unsigned long long acc[2] = {0ull, 0ull};
    int iters = (n + 7) >> 3;
    for (int it = 0; it < iters; it++) {
        int4 e[4];
        #pragma unroll
        for (int q = 0; q < 4; q++) e[q] = b4[it * 4 + q];
        #pragma unroll
        for (int q = 0; q < 4; q++) {
            int col   = hi ? e[q].z : e[q].x;
            int vbits = hi ? e[q].w : e[q].y;
            uint2 u = *reinterpret_cast<const uint2*>(
                g_Zh + (size_t)col * 128 + 64 + sub * 4);
            unsigned long long v2 = pack2(__int_as_float(vbits));
            fma2(acc[0], h2f2(u.x), v2);
            fma2(acc[1], h2f2(u.y), v2);
        }
    }
    #pragma unroll
    for (int q = 0; q < 2; q++) {
        unsigned long long o = __shfl_xor_sync(0xffffffffu, acc[q], 16);
        add2(acc[q], o);
    }
    if (hi == 0) {
        float2 a0 = unpack2(acc[0]);
        float2 a1 = unpack2(acc[1]);
        uint2 uu = *reinterpret_cast<const uint2*>(
            g_Zh + (size_t)gw * 128 + sub * 4);
        const __half* uh = reinterpret_cast<const __half*>(&uu);
        __half2 h0 = __floats2half2_rn(__half2float(uh[0]) + 2.f * a0.x,
                                       __half2float(uh[1]) + 2.f * a0.y);
        __half2 h1 = __floats2half2_rn(__half2float(uh[2]) + 2.f * a1.x,
                                       __half2float(uh[3]) + 2.f * a1.y);
        uint2 o;
        o.x = *reinterpret_cast<uint32_t*>(&h0);
        o.y = *reinterpret_cast<uint32_t*>(&h1);
        *reinterpret_cast<uint2*>(g_Qh + (size_t)gw * 64 + sub * 4) = o;
    }
}

// ---------------- final: marked rows, P[r] += sum v*Q[col]; clear mark ----------
__global__ void final_rows_kernel() {
    int gw = (blockIdx.x * blockDim.x + threadIdx.x) >> 5;
    if (gw >= NN) return;
    if (g_mark[gw] == 0) return;
    int lane = threadIdx.x & 31;
    int hi = lane >> 4;
    int sub = lane & 15;
    int n = g_cursor[gw];
    const int4* b4 = g_bkt4 + (size_t)gw * (BKT / 2);

    unsigned long long acc[2] = {0ull, 0ull};
    int iters = (n + 7) >> 3;
    for (int it = 0; it < iters; it++) {
        int4 e[4];
        #pragma unroll
        for (int q = 0; q < 4; q++) e[q] = b4[it * 4 + q];
        #pragma unroll
        for (int q = 0; q < 4; q++) {
            int col   = hi ? e[q].z : e[q].x;
            int vbits = hi ? e[q].w : e[q].y;
            uint2 u = *reinterpret_cast<const uint2*>(
                g_Qh + (size_t)col * 64 + sub * 4);
            unsigned long long v2 = pack2(__int_as_float(vbits));
            fma2(acc[0], h2f2(u.x), v2);
            fma2(acc[1], h2f2(u.y), v2);
        }
    }
    #pragma unroll
    for (int q = 0; q < 2; q++) {
        unsigned long long o = __shfl_xor_sync(0xffffffffu, acc[q], 16);
        add2(acc[q], o);
    }
    if (hi == 0) {
        float2 a0 = unpack2(acc[0]);
        float2 a1 = unpack2(acc[1]);
        float4* pr = reinterpret_cast<float4*>(g_P + (size_t)gw * 64) + sub;
        float4 p = *pr;
        p.x += a0.x; p.y += a0.y; p.z += a1.x; p.w += a1.y;
        *pr = p;
        if (sub == 0) g_mark[gw] = 0;   // self-clean
    }
}

// ---------------- output gather + cursor cleanup --------------------------------
__global__ void gather_out_kernel(const int* __restrict__ idx,
                                  float* __restrict__ out) {
    int i = blockIdx.x * blockDim.x + threadIdx.x;
    if (i < NN) g_cursor[i] = 0;           // self-clean for next launch
    if (i >= NIDX * 16) return;
    int n = i >> 4, f4 = i & 15;
    int r = idx[n];
    reinterpret_cast<float4*>(out + (size_t)n * 64)[f4] =
        reinterpret_cast<const float4*>(g_P + (size_t)r * 64)[f4];
}

// ---------------- fp16 tensor-core GEMM (mma.m16n8k16, fp32 accum) --------------
template <int BM, int BN, int BK, int WM, int WN, bool RELU, bool ADD_BIAS, bool HALF_OUT>
__global__ __launch_bounds__((BM / WM) * (BN / WN) * 32)
void gemm_f16_kernel(const __half* __restrict__ A, int lda,
                     const __half* __restrict__ B, int ldb,
                     const float* __restrict__ bias,
                     void* __restrict__ Cv, int ldc,
                     int M, int Ktot) {
    constexpr int WARPS_M = BM / WM;
    constexpr int WARPS_N = BN / WN;
    constexpr int THREADS = WARPS_M * WARPS_N * 32;
    constexpr int MT = WM / 16;
    constexpr int NT = WN / 8;
    constexpr int LDS = BK + 8;
    constexpr int HP = BK / 4;
    constexpr int A_IT = BM * HP / THREADS;
    constexpr int B_IT = BN * HP / THREADS;

    __shared__ __half As[BM][LDS];
    __shared__ __half Bs[BN][LDS];

    int tid = threadIdx.x;
    int lane = tid & 31, wid = tid >> 5;
    int gid = lane >> 2;
    int tig2 = (lane & 3) * 2;
    int wm = (wid / WARPS_N) * WM;
    int wn = (wid % WARPS_N) * WN;
    int m0 = blockIdx.y * BM;
    int n0 = blockIdx.x * BN;

    float acc[MT][NT][4];
    #pragma unroll
    for (int mt = 0; mt < MT; mt++)
        #pragma unroll
        for (int nt = 0; nt < NT; nt++)
            #pragma unroll
            for (int q = 0; q < 4; q++) acc[mt][nt][q] = 0.f;

    for (int k0 = 0; k0 < Ktot; k0 += BK) {
        #pragma unroll
        for (int it = 0; it < A_IT; it++) {
            int g = tid + it * THREADS;
            int r = g / HP, c = (g % HP) * 4;
            int m = m0 + r;
            uint2 v = make_uint2(0u, 0u);
            if (m < M)
                v = *reinterpret_cast<const uint2*>(A + (size_t)m * lda + k0 + c);
            *reinterpret_cast<uint2*>(&As[r][c]) = v;
        }
        #pragma unroll
        for (int it = 0; it < B_IT; it++) {
            int g = tid + it * THREADS;
            int r = g / HP, c = (g % HP) * 4;
            *reinterpret_cast<uint2*>(&Bs[r][c]) =
                *reinterpret_cast<const uint2*>(B + (size_t)(n0 + r) * ldb + k0 + c);
        }
        __syncthreads();
        #pragma unroll
        for (int kk = 0; kk < BK; kk += 16) {
            uint32_t af[MT][4], bf[NT][2];
            #pragma unroll
            for (int mt = 0; mt < MT; mt++) {
                int r = wm + mt * 16 + gid;
                af[mt][0] = *reinterpret_cast<const uint32_t*>(&As[r][kk + tig2]);
                af[mt][1] = *reinterpret_cast<const uint32_t*>(&As[r + 8][kk + tig2]);
                af[mt][2] = *reinterpret_cast<const uint32_t*>(&As[r][kk + tig2 + 8]);
                af[mt][3] = *reinterpret_cast<const uint32_t*>(&As[r + 8][kk + tig2 + 8]);
            }
            #pragma unroll
            for (int nt = 0; nt < NT; nt++) {
                int n = wn + nt * 8 + gid;
                bf[nt][0] = *reinterpret_cast<const uint32_t*>(&Bs[n][kk + tig2]);
                bf[nt][1] = *reinterpret_cast<const uint32_t*>(&Bs[n][kk + tig2 + 8]);
            }
            #pragma unroll
            for (int mt = 0; mt < MT; mt++)
                #pragma unroll
                for (int nt = 0; nt < NT; nt++)
                    asm volatile(
                        "mma.sync.aligned.m16n8k16.row.col.f32.f16.f16.f32 "
                        "{%0,%1,%2,%3}, {%4,%5,%6,%7}, {%8,%9}, {%0,%1,%2,%3};"
                        : "+f"(acc[mt][nt][0]), "+f"(acc[mt][nt][1]),
                          "+f"(acc[mt][nt][2]), "+f"(acc[mt][nt][3])
                        : "r"(af[mt][0]), "r"(af[mt][1]), "r"(af[mt][2]), "r"(af[mt][3]),
                          "r"(bf[nt][0]), "r"(bf[nt][1]));
        }
        __syncthreads();
    }

    #pragma unroll
    for (int mt = 0; mt < MT; mt++) {
        int r0 = m0 + wm + mt * 16 + gid;
        #pragma unroll
        for (int nt = 0; nt < NT; nt++) {
            int n = n0 + wn + nt * 8 + tig2;
            float bx = 0.f, by = 0.f;
            if (ADD_BIAS) { bx = bias[n]; by = bias[n + 1]; }
            float2 o0, o1;
            o0.x = acc[mt][nt][0] + bx; o0.y = acc[mt][nt][1] + by;
            o1.x = acc[mt][nt][2] + bx; o1.y = acc[mt][nt][3] + by;
            if (RELU) {
                o0.x = fmaxf(o0.x, 0.f); o0.y = fmaxf(o0.y, 0.f);
                o1.x = fmaxf(o1.x, 0.f); o1.y = fmaxf(o1.y, 0.f);
            }
            if (HALF_OUT) {
                __half* C = (__half*)Cv;
                if (r0 < M)
                    *reinterpret_cast<__half2*>(C + (size_t)r0 * ldc + n) =
                        __floats2half2_rn(o0.x, o0.y);
                if (r0 + 8 < M)
                    *reinterpret_cast<__half2*>(C + (size_t)(r0 + 8) * ldc + n) =
                        __floats2half2_rn(o1.x, o1.y);
            } else {
                float* C = (float*)Cv;
                if (r0 < M)
                    *reinterpret_cast<float2*>(C + (size_t)r0 * ldc + n) = o0;
                if (r0 + 8 < M)
                    *reinterpret_cast<float2*>(C + (size_t)(r0 + 8) * ldc + n) = o1;
            }
        }
    }
}

// ---------------- launch ----------------------------------------------------------
extern "C" void kernel_launch(void* const* d_in, const int* in_sizes, int n_in,
                              void* d_out, int out_size) {
    const float* x    = (const float*)d_in[0];
    const float* vals = (const float*)d_in[1];
    const float* W1   = (const float*)d_in[2];
    const float* b1   = (const float*)d_in[3];
    const float* W2   = (const float*)d_in[4];
    const float* b2   = (const float*)d_in[5];
    const int*   rows = (const int*)d_in[6];
    const int*   cols = (const int*)d_in[7];
    const int*   idx  = (const int*)d_in[8];
    float*       out  = (float*)d_out;

    float  *p;
    __half *bh, *hh, *zh, *w1t, *w2catT, *w2dT;
    cudaGetSymbolAddress((void**)&p,      g_P);
    cudaGetSymbolAddress((void**)&bh,     g_Bh);
    cudaGetSymbolAddress((void**)&hh,     g_Hh);
    cudaGetSymbolAddress((void**)&zh,     g_Zh);
    cudaGetSymbolAddress((void**)&w1t,    g_W1t);
    cudaGetSymbolAddress((void**)&w2catT, g_W2catT);
    cudaGetSymbolAddress((void**)&w2dT,   g_W2dT);

    int warp_blocks = cdiv(NN * 32, 256);

    // 0: bucket scatter + x->fp16 + weight prep + mark output rows
    scatter_prep_kernel<<<cdiv(NNZE, 256), 256>>>(rows, cols, vals, x, W1, W2, idx);
    // 1: T1 = L x
    spmm_bh_kernel<false><<<warp_blocks, 256>>>(0, 128);
    // 2: T2 = 2 L T1 - x
    spmm_bh_kernel<true><<<warp_blocks, 256>>>(128, 256);
    // 3: H = relu(Basis @ W1 + b1) -> fp16   (profiled launch)
    {
        dim3 grid(2, cdiv(NN, 128));
        gemm_f16_kernel<128, 128, 32, 32, 64, true, true, true><<<grid, 256>>>(
            bh, 384, w1t, 384, b1, hh, 256, NN, 384);
    }
    // 4: Z = H @ [W2_1 | W2_2] -> fp16
    {
        dim3 grid(1, cdiv(NN, 128));
        gemm_f16_kernel<128, 128, 32, 32, 64, false, false, true><<<grid, 256>>>(
            hh, 256, w2catT, 256, nullptr, zh, 128, NN, 256);
    }
    // 5: P = H @ (W2_0 - W2_2) + b2 -> fp32
    {
        dim3 grid(1, cdiv(NN, 128));
        gemm_f16_kernel<128, 64, 32, 32, 32, false, true, false><<<grid, 256>>>(
            hh, 256, w2dT, 256, b2, p, 64, NN, 256);
    }
    // 6: Q = U + 2 * (L V)
    spmm_q_kernel<<<warp_blocks, 256>>>();
    // 7: marked rows: P[r] += sum v * Q[col]   (clears marks)
    final_rows_kernel<<<warp_blocks, 256>>>();
    // 8: out[i] = P[idx[i]]  (+ cursor cleanup)
    gather_out_kernel<<<cdiv(NIDX * 16, 256), 256>>>(idx, out);
}

// round 14
// speedup vs baseline: 1.5657x; 1.0719x over previous
#include <cuda_runtime.h>
#include <cuda_fp16.h>
#include <cstdint>

#define NN   100000
#define NNZE 3200000
#define NIDX 50000
#define BKT  128          // bucket capacity per row (max degree ~60)

static inline int cdiv(int a, int b) { return (a + b - 1) / b; }

// ---------------- scratch (device globals; zero-initialized at module load) ----
__device__ int    g_cursor[NN];     // degree counters; cleared in gather_out
__device__ int    g_mark[NN];       // set in scatter_prep, cleared by final_rows
__device__ int4   g_bkt4[(size_t)NN * (BKT / 2)];   // 2 edges per int4; unused = 0
// fp16 basis: [N][384] = [x | T1 | T2]
__device__ __half g_Bh[(size_t)NN * 384];
// fp16 hidden: [N][256]
__device__ __half g_Hh[(size_t)NN * 256];
// fp16 Z: [N][128]  ([0:64)=U, [64:128)=V)
__device__ __half g_Zh[(size_t)NN * 128];
// fp16 Q = U + 2*(L V): [N][64]
__device__ __half g_Qh[(size_t)NN * 64];
// P = H @ (W2_0 - W2_2) + b2, fp32; final pass accumulates in place
__device__ float  g_P[(size_t)NN * 64];
// fp16 transposed weights (n-major, K contiguous)
__device__ __half g_W1t[256 * 384];
__device__ __half g_W2catT[128 * 256];
__device__ __half g_W2dT[64 * 256];

// ---------------- packed f32x2 helpers ---------------------------------------
__device__ __forceinline__ unsigned long long pack2(float v) {
    unsigned long long r;
    asm("mov.b64 %0, {%1, %1};" : "=l"(r) : "f"(v));
    return r;
}
__device__ __forceinline__ unsigned long long h2f2(uint32_t h) {
    unsigned long long r;
    asm("{\n\t"
        ".reg .b16 l, h;\n\t"
        ".reg .f32 fl, fh;\n\t"
        "mov.b32 {l, h}, %1;\n\t"
        "cvt.f32.f16 fl, l;\n\t"
        "cvt.f32.f16 fh, h;\n\t"
        "mov.b64 %0, {fl, fh};\n\t"
        "}" : "=l"(r) : "r"(h));
    return r;
}
__device__ __forceinline__ void fma2(unsigned long long& acc,
                                     unsigned long long a, unsigned long long b) {
    asm("fma.rn.f32x2 %0, %1, %2, %0;" : "+l"(acc) : "l"(a), "l"(b));
}
__device__ __forceinline__ void add2(unsigned long long& a, unsigned long long b) {
    asm("add.rn.f32x2 %0, %0, %1;" : "+l"(a) : "l"(b));
}
__device__ __forceinline__ float2 unpack2(unsigned long long a) {
    float2 f;
    asm("mov.b64 {%0, %1}, %2;" : "=f"(f.x), "=f"(f.y) : "l"(a));
    return f;
}
__device__ __forceinline__ uint2 f4_to_h4(float4 v) {
    __half2 h0 = __floats2half2_rn(v.x, v.y);
    __half2 h1 = __floats2half2_rn(v.z, v.w);
    uint2 u;
    u.x = *reinterpret_cast<uint32_t*>(&h0);
    u.y = *reinterpret_cast<uint32_t*>(&h1);
    return u;
}

// ---------------- cp.async helpers --------------------------------------------
__device__ __forceinline__ void cp_async16(uint32_t dst, const void* src, int sz) {
    asm volatile("cp.async.ca.shared.global [%0], [%1], 16, %2;"
                 :: "r"(dst), "l"(src), "r"(sz));
}
__device__ __forceinline__ void cp_commit() {
    asm volatile("cp.async.commit_group;");
}
template <int NWAIT>
__device__ __forceinline__ void cp_wait() {
    asm volatile("cp.async.wait_group %0;" :: "n"(NWAIT));
}

// ---------------- scatter + x->fp16 + weight prep + marking (one launch) -------
__global__ void scatter_prep_kernel(const int* __restrict__ rows,
                                    const int* __restrict__ cols,
                                    const float* __restrict__ vals,
                                    const float* __restrict__ x,
                                    const float* __restrict__ W1,
                                    const float* __restrict__ W2,
                                    const int* __restrict__ idx) {
    int i = blockIdx.x * blockDim.x + threadIdx.x;
    if (i < NNZE) {
        int r = rows[i];
        int pos = atomicAdd(&g_cursor[r], 1);
        reinterpret_cast<int2*>(g_bkt4)[(size_t)r * BKT + pos] =
            make_int2(cols[i], __float_as_int(vals[i]));
    }
    if (i < NN * 32) {
        int n = i >> 5, f4 = i & 31;
        float4 v = reinterpret_cast<const float4*>(x)[i];
        reinterpret_cast<uint2*>(g_Bh + (size_t)n * 384)[f4] = f4_to_h4(v);
    }
    if (i < 256 * 384) {              // W1t[j][t], t = k*128+f
        int j = i / 384, t = i % 384;
        int k = t / 128, f = t % 128;
        g_W1t[i] = __float2half(W1[(f * 3 + k) * 256 + j]);
    }
    if (i < 128 * 256) {              // W2catT[j][f]
        int j = i / 256, f = i % 256;
        int kk = (j < 64) ? 1 : 2;
        int jj = (j < 64) ? j : (j - 64);
        g_W2catT[i] = __float2half(W2[(f * 3 + kk) * 64 + jj]);
    }
    if (i < 64 * 256) {               // W2dT[j][f] = W2_0 - W2_2
        int j = i / 256, f = i % 256;
        g_W2dT[i] = __float2half(W2[(f * 3 + 0) * 64 + j] - W2[(f * 3 + 2) * 64 + j]);
    }
    if (i < NIDX) g_mark[idx[i]] = 1;
}

// ---------------- SpMM over fp16 basis: half-warp edge pairing -----------------
template <bool SUB>
__global__ void spmm_bh_kernel(int src_off, int dst_off) {
    int gw = (blockIdx.x * blockDim.x + threadIdx.x) >> 5;
    if (gw >= NN) return;
    int lane = threadIdx.x & 31;
    int hi = lane >> 4;          // which edge of each pair
    int sub = lane & 15;         // 16B feature slice
    int n = g_cursor[gw];
    const int4* b4 = g_bkt4 + (size_t)gw * (BKT / 2);

    unsigned long long acc[4] = {0ull, 0ull, 0ull, 0ull};

    int iters = (n + 7) >> 3;    // buckets zero-padded -> no tail loop
    for (int it = 0; it < iters; it++) {
        int4 e[4];
        #pragma unroll
        for (int q = 0; q < 4; q++) e[q] = b4[it * 4 + q];
        #pragma unroll
        for (int q = 0; q < 4; q++) {
            int col   = hi ? e[q].z : e[q].x;
            int vbits = hi ? e[q].w : e[q].y;
            uint4 u = *reinterpret_cast<const uint4*>(
                g_Bh + (size_t)col * 384 + src_off + sub * 8);
            unsigned long long v2 = pack2(__int_as_float(vbits));
            fma2(acc[0], h2f2(u.x), v2);
            fma2(acc[1], h2f2(u.y), v2);
            fma2(acc[2], h2f2(u.z), v2);
            fma2(acc[3], h2f2(u.w), v2);
        }
    }
    #pragma unroll
    for (int q = 0; q < 4; q++) {
        unsigned long long o = __shfl_xor_sync(0xffffffffu, acc[q], 16);
        add2(acc[q], o);
    }
    if (hi == 0) {
        float f[8];
        #pragma unroll
        for (int q = 0; q < 4; q++) {
            float2 t = unpack2(acc[q]);
            f[2 * q] = t.x; f[2 * q + 1] = t.y;
        }
        if (SUB) {
            uint4 su = *reinterpret_cast<const uint4*>(
                g_Bh + (size_t)gw * 384 + sub * 8);
            const __half* sh = reinterpret_cast<const __half*>(&su);
            #pragma unroll
            for (int q = 0; q < 8; q++)
                f[q] = 2.f * f[q] - __half2float(sh[q]);
        }
        uint4 o;
        __half2 h0 = __floats2half2_rn(f[0], f[1]);
        __half2 h1 = __floats2half2_rn(f[2], f[3]);
        __half2 h2 = __floats2half2_rn(f[4], f[5]);
        __half2 h3 = __floats2half2_rn(f[6], f[7]);
        o.x = *reinterpret_cast<uint32_t*>(&h0);
        o.y = *reinterpret_cast<uint32_t*>(&h1);
        o.z = *reinterpret_cast<uint32_t*>(&h2);
        o.w = *reinterpret_cast<uint32_t*>(&h3);
        *reinterpret_cast<uint4*>(g_Bh + (size_t)gw * 384 + dst_off + sub * 8) = o;
    }
}

// ---------------- Q = U + 2*(L V): rows 64 halves (128B), paired edges ---------
__global__ void spmm_q_kernel() {
    int gw = (blockIdx.x * blockDim.x + threadIdx.x) >> 5;
    if (gw >= NN) return;
    int lane = threadIdx.x & 31;
    int hi = lane >> 4;
    int sub = lane & 15;         // 8B slice (4 halves)
    int n = g_cursor[gw];
    const int4* b4 = g_bkt4 + (size_t)gw * (BKT / 2);

    unsigned long long acc[2] = {0ull, 0ull};
    int iters = (n + 7) >> 3;
    for (int it = 0; it < iters; it++) {
        int4 e[4];
        #pragma unroll
        for (int q = 0; q < 4; q++) e[q] = b4[it * 4 + q];
        #pragma unroll
        for (int q = 0; q < 4; q++) {
            int col   = hi ? e[q].z : e[q].x;
            int vbits = hi ? e[q].w : e[q].y;
            uint2 u = *reinterpret_cast<const uint2*>(
                g_Zh + (size_t)col * 128 + 64 + sub * 4);
            unsigned long long v2 = pack2(__int_as_float(vbits));
            fma2(acc[0], h2f2(u.x), v2);
            fma2(acc[1], h2f2(u.y), v2);
        }
    }
    #pragma unroll
    for (int q = 0; q < 2; q++) {
        unsigned long long o = __shfl_xor_sync(0xffffffffu, acc[q], 16);
        add2(acc[q], o);
    }
    if (hi == 0) {
        float2 a0 = unpack2(acc[0]);
        float2 a1 = unpack2(acc[1]);
        uint2 uu = *reinterpret_cast<const uint2*>(
            g_Zh + (size_t)gw * 128 + sub * 4);
        const __half* uh = reinterpret_cast<const __half*>(&uu);
        __half2 h0 = __floats2half2_rn(__half2float(uh[0]) + 2.f * a0.x,
                                       __half2float(uh[1]) + 2.f * a0.y);
        __half2 h1 = __floats2half2_rn(__half2float(uh[2]) + 2.f * a1.x,
                                       __half2float(uh[3]) + 2.f * a1.y);
        uint2 o;
        o.x = *reinterpret_cast<uint32_t*>(&h0);
        o.y = *reinterpret_cast<uint32_t*>(&h1);
        *reinterpret_cast<uint2*>(g_Qh + (size_t)gw * 64 + sub * 4) = o;
    }
}

// ---------------- final: marked rows, P[r] += sum v*Q[col]; clear mark ----------
__global__ void final_rows_kernel() {
    int gw = (blockIdx.x * blockDim.x + threadIdx.x) >> 5;
    if (gw >= NN) return;
    if (g_mark[gw] == 0) return;
    int lane = threadIdx.x & 31;
    int hi = lane >> 4;
    int sub = lane & 15;
    int n = g_cursor[gw];
    const int4* b4 = g_bkt4 + (size_t)gw * (BKT / 2);

    unsigned long long acc[2] = {0ull, 0ull};
    int iters = (n + 7) >> 3;
    for (int it = 0; it < iters; it++) {
        int4 e[4];
        #pragma unroll
        for (int q = 0; q < 4; q++) e[q] = b4[it * 4 + q];
        #pragma unroll
        for (int q = 0; q < 4; q++) {
            int col   = hi ? e[q].z : e[q].x;
            int vbits = hi ? e[q].w : e[q].y;
            uint2 u = *reinterpret_cast<const uint2*>(
                g_Qh + (size_t)col * 64 + sub * 4);
            unsigned long long v2 = pack2(__int_as_float(vbits));
            fma2(acc[0], h2f2(u.x), v2);
            fma2(acc[1], h2f2(u.y), v2);
        }
    }
    #pragma unroll
    for (int q = 0; q < 2; q++) {
        unsigned long long o = __shfl_xor_sync(0xffffffffu, acc[q], 16);
        add2(acc[q], o);
    }
    if (hi == 0) {
        float2 a0 = unpack2(acc[0]);
        float2 a1 = unpack2(acc[1]);
        float4* pr = reinterpret_cast<float4*>(g_P + (size_t)gw * 64) + sub;
        float4 p = *pr;
        p.x += a0.x; p.y += a0.y; p.z += a1.x; p.w += a1.y;
        *pr = p;
        if (sub == 0) g_mark[gw] = 0;   // self-clean
    }
}

// ---------------- output gather + cursor cleanup --------------------------------
__global__ void gather_out_kernel(const int* __restrict__ idx,
                                  float* __restrict__ out) {
    int i = blockIdx.x * blockDim.x + threadIdx.x;
    if (i < NN) g_cursor[i] = 0;           // self-clean for next launch
    if (i >= NIDX * 16) return;
    int n = i >> 4, f4 = i & 15;
    int r = idx[n];
    reinterpret_cast<float4*>(out + (size_t)n * 64)[f4] =
        reinterpret_cast<const float4*>(g_P + (size_t)r * 64)[f4];
}

// ---------------- fp16 tensor-core GEMM: cp.async double-buffer + ldmatrix ------
// A: fp16 [M][lda] row-major.  B: fp16 [Ntot][ldb] n-major (K contiguous).
template <int BM, int BN, int BK, int WM, int WN, bool RELU, bool ADD_BIAS, bool HALF_OUT>
__global__ __launch_bounds__((BM / WM) * (BN / WN) * 32)
void gemm_f16_kernel(const __half* __restrict__ A, int lda,
                     const __half* __restrict__ B, int ldb,
                     const float* __restrict__ bias,
                     void* __restrict__ Cv, int ldc,
                     int M, int Ktot) {
    constexpr int WARPS_M = BM / WM;
    constexpr int WARPS_N = BN / WN;
    constexpr int THREADS = WARPS_M * WARPS_N * 32;
    constexpr int MT = WM / 16;
    constexpr int NT = WN / 8;
    constexpr int LDS = BK + 8;          // halves; 80B stride -> conflict-free ldmatrix
    constexpr int HP = BK / 8;           // 16B chunks per row
    constexpr int A_IT = BM * HP / THREADS;
    constexpr int B_IT = (BN * HP + THREADS - 1) / THREADS;

    __shared__ __half As[2][BM][LDS];
    __shared__ __half Bs[2][BN][LDS];

    int tid = threadIdx.x;
    int lane = tid & 31, wid = tid >> 5;
    int gid = lane >> 2;
    int tig2 = (lane & 3) * 2;
    int wm = (wid / WARPS_N) * WM;
    int wn = (wid % WARPS_N) * WN;
    int m0 = blockIdx.y * BM;
    int n0 = blockIdx.x * BN;

    uint32_t as_base = (uint32_t)__cvta_generic_to_shared(&As[0][0][0]);
    uint32_t bs_base = (uint32_t)__cvta_generic_to_shared(&Bs[0][0][0]);
    constexpr uint32_t A_STAGE = BM * LDS * 2;   // bytes
    constexpr uint32_t B_STAGE = BN * LDS * 2;

    // ldmatrix lane address offsets (bytes within a stage)
    // A x4: lanes0-7 rows m0-7 @k0, 8-15 rows m8-15 @k0, 16-23 m0-7 @k8, 24-31 m8-15 @k8
    uint32_t offA[MT];
    #pragma unroll
    for (int mt = 0; mt < MT; mt++) {
        int r = wm + mt * 16 + (lane & 7) + ((lane >> 3) & 1) * 8;
        int c = (lane >> 4) * 8;
        offA[mt] = (uint32_t)((r * LDS + c) * 2);
    }
    // B x4: lanes0-7 rows n0-7 @k0, 8-15 rows n0-7 @k8, 16-23 n8-15 @k0, 24-31 n8-15 @k8
    uint32_t offB[NT / 2];
    #pragma unroll
    for (int nt2 = 0; nt2 < NT / 2; nt2++) {
        int r = wn + nt2 * 16 + (lane & 7) + (lane >> 4) * 8;
        int c = ((lane >> 3) & 1) * 8;
        offB[nt2] = (uint32_t)((r * LDS + c) * 2);
    }

    float acc[MT][NT][4];
    #pragma unroll
    for (int mt = 0; mt < MT; mt++)
        #pragma unroll
        for (int nt = 0; nt < NT; nt++)
            #pragma unroll
            for (int q = 0; q < 4; q++) acc[mt][nt][q] = 0.f;

    const int T = Ktot / BK;

    auto load_tile = [&](int t, int st) {
        int k0 = t * BK;
        #pragma unroll
        for (int it = 0; it < A_IT; it++) {
            int g = tid + it * THREADS;
            int r = g / HP, c = (g % HP) * 8;
            int m = m0 + r;
            int sz = (m < M) ? 16 : 0;
            int mc = (m < M) ? m : 0;
            cp_async16(as_base + st * A_STAGE + (uint32_t)((r * LDS + c) * 2),
                       A + (size_t)mc * lda + k0 + c, sz);
        }
        #pragma unroll
        for (int it = 0; it < B_IT; it++) {
            int g = tid + it * THREADS;
            if (g < BN * HP) {
                int r = g / HP, c = (g % HP) * 8;
                cp_async16(bs_base + st * B_STAGE + (uint32_t)((r * LDS + c) * 2),
                           B + (size_t)(n0 + r) * ldb + k0 + c, 16);
            }
        }
        cp_commit();
    };

    load_tile(0, 0);
    for (int t = 0; t < T; t++) {
        int st = t & 1;
        if (t + 1 < T) {
            load_tile(t + 1, st ^ 1);
            cp_wait<1>();
        } else {
            cp_wait<0>();
        }
        __syncthreads();

        #pragma unroll
        for (int kk = 0; kk < BK; kk += 16) {
            uint32_t af[MT][4], bf[NT][2];
            #pragma unroll
            for (int mt = 0; mt < MT; mt++) {
                uint32_t addr = as_base + st * A_STAGE + offA[mt] + kk * 2;
                asm volatile(
                    "ldmatrix.sync.aligned.m8n8.x4.shared.b16 {%0,%1,%2,%3}, [%4];"
                    : "=r"(af[mt][0]), "=r"(af[mt][1]),
                      "=r"(af[mt][2]), "=r"(af[mt][3]) : "r"(addr));
            }
            #pragma unroll
            for (int nt2 = 0; nt2 < NT / 2; nt2++) {
                uint32_t addr = bs_base + st * B_STAGE + offB[nt2] + kk * 2;
                asm volatile(
                    "ldmatrix.sync.aligned.m8n8.x4.shared.b16 {%0,%1,%2,%3}, [%4];"
                    : "=r"(bf[2 * nt2][0]), "=r"(bf[2 * nt2][1]),
                      "=r"(bf[2 * nt2 + 1][0]), "=r"(bf[2 * nt2 + 1][1]) : "r"(addr));
            }
            #pragma unroll
            for (int mt = 0; mt < MT; mt++)
                #pragma unroll
                for (int nt = 0; nt < NT; nt++)
                    asm volatile(
                        "mma.sync.aligned.m16n8k16.row.col.f32.f16.f16.f32 "
                        "{%0,%1,%2,%3}, {%4,%5,%6,%7}, {%8,%9}, {%0,%1,%2,%3};"
                        : "+f"(acc[mt][nt][0]), "+f"(acc[mt][nt][1]),
                          "+f"(acc[mt][nt][2]), "+f"(acc[mt][nt][3])
                        : "r"(af[mt][0]), "r"(af[mt][1]), "r"(af[mt][2]), "r"(af[mt][3]),
                          "r"(bf[nt][0]), "r"(bf[nt][1]));
        }
        __syncthreads();
    }

    #pragma unroll
    for (int mt = 0; mt < MT; mt++) {
        int r0 = m0 + wm + mt * 16 + gid;
        #pragma unroll
        for (int nt = 0; nt < NT; nt++) {
            int n = n0 + wn + nt * 8 + tig2;
            float bx = 0.f, by = 0.f;
            if (ADD_BIAS) { bx = bias[n]; by = bias[n + 1]; }
            float2 o0, o1;
            o0.x = acc[mt][nt][0] + bx; o0.y = acc[mt][nt][1] + by;
            o1.x = acc[mt][nt][2] + bx; o1.y = acc[mt][nt][3] + by;
            if (RELU) {
                o0.x = fmaxf(o0.x, 0.f); o0.y = fmaxf(o0.y, 0.f);
                o1.x = fmaxf(o1.x, 0.f); o1.y = fmaxf(o1.y, 0.f);
            }
            if (HALF_OUT) {
                __half* C = (__half*)Cv;
                if (r0 < M)
                    *reinterpret_cast<__half2*>(C + (size_t)r0 * ldc + n) =
                        __floats2half2_rn(o0.x, o0.y);
                if (r0 + 8 < M)
                    *reinterpret_cast<__half2*>(C + (size_t)(r0 + 8) * ldc + n) =
                        __floats2half2_rn(o1.x, o1.y);
            } else {
                float* C = (float*)Cv;
                if (r0 < M)
                    *reinterpret_cast<float2*>(C + (size_t)r0 * ldc + n) = o0;
                if (r0 + 8 < M)
                    *reinterpret_cast<float2*>(C + (size_t)(r0 + 8) * ldc + n) = o1;
            }
        }
    }
}

// ---------------- launch ----------------------------------------------------------
extern "C" void kernel_launch(void* const* d_in, const int* in_sizes, int n_in,
                              void* d_out, int out_size) {
    const float* x    = (const float*)d_in[0];
    const float* vals = (const float*)d_in[1];
    const float* W1   = (const float*)d_in[2];
    const float* b1   = (const float*)d_in[3];
    const float* W2   = (const float*)d_in[4];
    const float* b2   = (const float*)d_in[5];
    const int*   rows = (const int*)d_in[6];
    const int*   cols = (const int*)d_in[7];
    const int*   idx  = (const int*)d_in[8];
    float*       out  = (float*)d_out;

    float  *p;
    __half *bh, *hh, *zh, *w1t, *w2catT, *w2dT;
    cudaGetSymbolAddress((void**)&p,      g_P);
    cudaGetSymbolAddress((void**)&bh,     g_Bh);
    cudaGetSymbolAddress((void**)&hh,     g_Hh);
    cudaGetSymbolAddress((void**)&zh,     g_Zh);
    cudaGetSymbolAddress((void**)&w1t,    g_W1t);
    cudaGetSymbolAddress((void**)&w2catT, g_W2catT);
    cudaGetSymbolAddress((void**)&w2dT,   g_W2dT);

    int warp_blocks = cdiv(NN * 32, 256);

    // 0: bucket scatter + x->fp16 + weight prep + mark output rows
    scatter_prep_kernel<<<cdiv(NNZE, 256), 256>>>(rows, cols, vals, x, W1, W2, idx);
    // 1: T1 = L x
    spmm_bh_kernel<false><<<warp_blocks, 256>>>(0, 128);
    // 2: T2 = 2 L T1 - x
    spmm_bh_kernel<true><<<warp_blocks, 256>>>(128, 256);
    // 3: H = relu(Basis @ W1 + b1) -> fp16   (profiled launch)
    {
        dim3 grid(2, cdiv(NN, 128));
        gemm_f16_kernel<128, 128, 32, 32, 64, true, true, true><<<grid, 256>>>(
            bh, 384, w1t, 384, b1, hh, 256, NN, 384);
    }
    // 4: Z = H @ [W2_1 | W2_2] -> fp16
    {
        dim3 grid(1, cdiv(NN, 128));
        gemm_f16_kernel<128, 128, 32, 32, 64, false, false, true><<<grid, 256>>>(
            hh, 256, w2catT, 256, nullptr, zh, 128, NN, 256);
    }
    // 5: P = H @ (W2_0 - W2_2) + b2 -> fp32
    {
        dim3 grid(1, cdiv(NN, 128));
        gemm_f16_kernel<128, 64, 32, 32, 32, false, true, false><<<grid, 256>>>(
            hh, 256, w2dT, 256, b2, p, 64, NN, 256);
    }
    // 6: Q = U + 2 * (L V)
    spmm_q_kernel<<<warp_blocks, 256>>>();
    // 7: marked rows: P[r] += sum v * Q[col]   (clears marks)
    final_rows_kernel<<<warp_blocks, 256>>>();
    // 8: out[i] = P[idx[i]]  (+ cursor cleanup)
    gather_out_kernel<<<cdiv(NIDX * 16, 256), 256>>>(idx, out);
}